// round 8
// baseline (speedup 1.0000x reference)
#include <cuda_runtime.h>
#include <cuda_bf16.h>
#include <math.h>

#define BB 64
#define SS 512
#define HH 1024
#define VV 50257

// ---------------- scratch (device globals; no allocations allowed) ----------
__device__ float g_p[BB * HH];            // h @ W1^T + attn_b
__device__ float g_scores[BB * SS];       // pre-softmax attention scores
__device__ float g_context[BB * HH];
__device__ float g_x[BB * 2 * HH];        // [embedded ; context]
__device__ float g_gi[BB * 3 * HH];
__device__ float g_gh[BB * 3 * HH];
__device__ float g_hnew[BB * HH];

// ---------------- zero scores ----------------
__global__ void zero_scores_kernel() {
    int i = blockIdx.x * 256 + threadIdx.x;
    if (i < BB * SS) g_scores[i] = 0.f;
}

// ---------------- generic small GEMM: C[m,n] = bias[n] + sum_k A[m,k]*B[n,k]
// M fixed = 64 (batch). grid.x = ceil(N/64), block = 256.
__global__ void small_gemm(const float* __restrict__ A, int lda,
                           const float* __restrict__ Bw, int ldb,
                           const float* __restrict__ bias,
                           float* __restrict__ C, int N, int K) {
    __shared__ float As[16][64];
    __shared__ float Bs[16][64];
    int tid = threadIdx.x;
    int n0 = blockIdx.x * 64;
    int tx = tid & 15, ty = tid >> 4;
    int lr = tid >> 2;          // 0..63
    int lk = (tid & 3) * 4;     // 0,4,8,12
    float acc[4][4];
#pragma unroll
    for (int i = 0; i < 4; i++)
#pragma unroll
        for (int j = 0; j < 4; j++) acc[i][j] = 0.f;

    bool bvalid = (n0 + lr) < N;
    const float* Ap = A + (size_t)lr * lda + lk;
    const float* Bp = Bw + (size_t)(n0 + lr) * ldb + lk;

    for (int k0 = 0; k0 < K; k0 += 16) {
        float4 a4 = *(const float4*)(Ap + k0);
        float4 b4 = bvalid ? *(const float4*)(Bp + k0) : make_float4(0.f, 0.f, 0.f, 0.f);
        As[lk + 0][lr] = a4.x; As[lk + 1][lr] = a4.y;
        As[lk + 2][lr] = a4.z; As[lk + 3][lr] = a4.w;
        Bs[lk + 0][lr] = b4.x; Bs[lk + 1][lr] = b4.y;
        Bs[lk + 2][lr] = b4.z; Bs[lk + 3][lr] = b4.w;
        __syncthreads();
#pragma unroll
        for (int k = 0; k < 16; k++) {
            float a[4], bb[4];
#pragma unroll
            for (int i = 0; i < 4; i++) a[i] = As[k][ty * 4 + i];
#pragma unroll
            for (int j = 0; j < 4; j++) bb[j] = Bs[k][tx * 4 + j];
#pragma unroll
            for (int i = 0; i < 4; i++)
#pragma unroll
                for (int j = 0; j < 4; j++) acc[i][j] += a[i] * bb[j];
        }
        __syncthreads();
    }
#pragma unroll
    for (int i = 0; i < 4; i++) {
        int m = ty * 4 + i;
#pragma unroll
        for (int j = 0; j < 4; j++) {
            int n = n0 + tx * 4 + j;
            if (n < N) C[(size_t)m * N + n] = acc[i][j] + bias[n];
        }
    }
}

// ---------------- attention energy GEMM with fused v*tanh reduction --------
// scores[b,s] += sum_{h in tile} v[h]*tanh( p[b,h] + sum_k enc[b,s,k]*W2[h,k] )
// grid: (B*S/128, H/128), block 256. 128x128 tile, K-chunk 8, 8x8 per thread.
__global__ void attn_energy_kernel(const float* __restrict__ enc,
                                   const float* __restrict__ attn_w,
                                   const float* __restrict__ v_w) {
    __shared__ float As[8][128];
    __shared__ float Bs[8][128];
    __shared__ float psh[128];
    __shared__ float vsh[128];
    __shared__ float sred[128];

    int tid = threadIdx.x;
    int r0 = blockIdx.x * 128;   // row base in [B*S]
    int n0 = blockIdx.y * 128;   // h base
    int b  = r0 / SS;            // 128 | 512, so constant per block
    int tx = tid & 15, ty = tid >> 4;
    int lr = tid >> 1;           // 0..127
    int lk = (tid & 1) * 4;      // 0 or 4

    const float* Aptr = enc + (size_t)(r0 + lr) * HH + lk;
    const float* Bptr = attn_w + (size_t)(n0 + lr) * (2 * HH) + HH + lk;

    if (tid < 128) {
        psh[tid]  = g_p[b * HH + n0 + tid];
        vsh[tid]  = v_w[n0 + tid];
        sred[tid] = 0.f;
    }

    float acc[8][8];
#pragma unroll
    for (int i = 0; i < 8; i++)
#pragma unroll
        for (int j = 0; j < 8; j++) acc[i][j] = 0.f;

    for (int k0 = 0; k0 < HH; k0 += 8) {
        float4 a4 = *(const float4*)(Aptr + k0);
        float4 b4 = *(const float4*)(Bptr + k0);
        As[lk + 0][lr] = a4.x; As[lk + 1][lr] = a4.y;
        As[lk + 2][lr] = a4.z; As[lk + 3][lr] = a4.w;
        Bs[lk + 0][lr] = b4.x; Bs[lk + 1][lr] = b4.y;
        Bs[lk + 2][lr] = b4.z; Bs[lk + 3][lr] = b4.w;
        __syncthreads();
#pragma unroll
        for (int k = 0; k < 8; k++) {
            float a[8], bb[8];
#pragma unroll
            for (int i = 0; i < 8; i++) a[i] = As[k][ty * 8 + i];
#pragma unroll
            for (int j = 0; j < 8; j++) bb[j] = Bs[k][tx * 8 + j];
#pragma unroll
            for (int i = 0; i < 8; i++)
#pragma unroll
                for (int j = 0; j < 8; j++) acc[i][j] += a[i] * bb[j];
        }
        __syncthreads();
    }

    // fused epilogue: tanh + v-weighted reduction over this h tile
#pragma unroll
    for (int i = 0; i < 8; i++) {
        float part = 0.f;
#pragma unroll
        for (int j = 0; j < 8; j++) {
            int hl = tx * 8 + j;
            part += vsh[hl] * tanhf(acc[i][j] + psh[hl]);
        }
        atomicAdd(&sred[ty * 8 + i], part);
    }
    __syncthreads();
    if (tid < 128) atomicAdd(&g_scores[r0 + tid], sred[tid]);
}

// ---------------- softmax over S per batch row (writes attn output) --------
__global__ void softmax_kernel(float* __restrict__ attn_out) {
    int b = blockIdx.x;
    int tid = threadIdx.x;      // 256 threads, 512 elems
    __shared__ float sh[256];
    float v0 = g_scores[b * SS + tid];
    float v1 = g_scores[b * SS + 256 + tid];
    float m = fmaxf(v0, v1);
    sh[tid] = m;
    __syncthreads();
    for (int o = 128; o > 0; o >>= 1) {
        if (tid < o) sh[tid] = fmaxf(sh[tid], sh[tid + o]);
        __syncthreads();
    }
    m = sh[0];
    __syncthreads();
    float e0 = expf(v0 - m), e1 = expf(v1 - m);
    sh[tid] = e0 + e1;
    __syncthreads();
    for (int o = 128; o > 0; o >>= 1) {
        if (tid < o) sh[tid] += sh[tid + o];
        __syncthreads();
    }
    float inv = 1.f / sh[0];
    attn_out[b * SS + tid]       = e0 * inv;
    attn_out[b * SS + 256 + tid] = e1 * inv;
}

// ---------------- context[b,h] = sum_s attn[b,s] * enc[b,s,h] --------------
// grid (B, H/128), block 128
__global__ void context_kernel(const float* __restrict__ enc,
                               const float* __restrict__ attn) {
    int b = blockIdx.x;
    int h = blockIdx.y * 128 + threadIdx.x;
    __shared__ float ash[SS];
    for (int i = threadIdx.x; i < SS; i += 128) ash[i] = attn[b * SS + i];
    __syncthreads();
    const float* ep = enc + (size_t)b * SS * HH + h;
    float acc = 0.f;
#pragma unroll 4
    for (int s = 0; s < SS; s++) acc += ash[s] * ep[(size_t)s * HH];
    g_context[b * HH + h] = acc;
}

// ---------------- x = [ emb[ids[b]] ; context[b] ] -------------------------
__global__ void xbuild_kernel(const int* __restrict__ ids,
                              const float* __restrict__ emb) {
    int idx = blockIdx.x * 256 + threadIdx.x;    // BB*2*HH
    int b = idx >> 11, k = idx & 2047;
    float v;
    if (k < HH) v = emb[(size_t)ids[b] * HH + k];
    else        v = g_context[b * HH + (k - HH)];
    g_x[idx] = v;
}

// ---------------- GRU elementwise: r,z,n -> h_new ---------------------------
__global__ void hnew_kernel(const float* __restrict__ hidden,
                            float* __restrict__ out_hidden) {
    int idx = blockIdx.x * 256 + threadIdx.x;    // BB*HH
    int b = idx >> 10, h = idx & 1023;
    int base = b * 3 * HH;
    float ir = g_gi[base + h];
    float iz = g_gi[base + HH + h];
    float in_ = g_gi[base + 2 * HH + h];
    float hr = g_gh[base + h];
    float hz = g_gh[base + HH + h];
    float hn = g_gh[base + 2 * HH + h];
    float r = 1.f / (1.f + expf(-(ir + hr)));
    float z = 1.f / (1.f + expf(-(iz + hz)));
    float n = tanhf(in_ + r * hn);
    float ho = hidden[idx];
    float hv = (1.f - z) * n + z * ho;
    g_hnew[idx] = hv;
    out_hidden[idx] = hv;
}

// ---------------- launch ----------------------------------------------------
extern "C" void kernel_launch(void* const* d_in, const int* in_sizes, int n_in,
                              void* d_out, int out_size) {
    const int*   ids    = (const int*)d_in[0];
    const float* hidden = (const float*)d_in[1];   // [1,B,H]
    const float* enc    = (const float*)d_in[2];   // [B,S,H]
    const float* emb    = (const float*)d_in[3];   // [V,H]
    const float* attn_w = (const float*)d_in[4];   // [H,2H]
    const float* attn_b = (const float*)d_in[5];   // [H]
    const float* v_w    = (const float*)d_in[6];   // [H]
    const float* w_ih   = (const float*)d_in[7];   // [3H,2H]
    const float* w_hh   = (const float*)d_in[8];   // [3H,H]
    const float* b_ih   = (const float*)d_in[9];   // [3H]
    const float* b_hh   = (const float*)d_in[10];  // [3H]
    const float* out_w  = (const float*)d_in[11];  // [V,H]
    const float* out_b  = (const float*)d_in[12];  // [V]

    float* out = (float*)d_out;
    float* out_pred   = out;                                   // [B,V]
    float* out_hidden = out + (size_t)BB * VV;                 // [1,B,H]
    float* out_attn   = out_hidden + (size_t)BB * HH;          // [B,S]

    float *p_p, *p_x, *p_gi, *p_gh, *p_hnew;
    cudaGetSymbolAddress((void**)&p_p,    g_p);
    cudaGetSymbolAddress((void**)&p_x,    g_x);
    cudaGetSymbolAddress((void**)&p_gi,   g_gi);
    cudaGetSymbolAddress((void**)&p_gh,   g_gh);
    cudaGetSymbolAddress((void**)&p_hnew, g_hnew);

    // 1. zero score accumulators
    zero_scores_kernel<<<(BB * SS + 255) / 256, 256>>>();

    // 2. p[b,h] = h @ W1^T + attn_b   (W1 = attn_w[:, :H])
    small_gemm<<<HH / 64, 256>>>(hidden, HH, attn_w, 2 * HH, attn_b, p_p, HH, HH);

    // 3. big fused energy GEMM + tanh + v reduction -> scores
    dim3 gattn(BB * SS / 128, HH / 128);
    attn_energy_kernel<<<gattn, 256>>>(enc, attn_w, v_w);

    // 4. softmax -> attn output
    softmax_kernel<<<BB, 256>>>(out_attn);

    // 5. context = attn @ enc
    context_kernel<<<dim3(BB, HH / 128), 128>>>(enc, out_attn);

    // 6. x = [embedded ; context]
    xbuild_kernel<<<(BB * 2 * HH) / 256, 256>>>(ids, emb);

    // 7. gi = x @ w_ih^T + b_ih ; gh = h @ w_hh^T + b_hh
    small_gemm<<<(3 * HH) / 64, 256>>>(p_x,    2 * HH, w_ih, 2 * HH, b_ih, p_gi, 3 * HH, 2 * HH);
    small_gemm<<<(3 * HH) / 64, 256>>>(hidden, HH,     w_hh, HH,     b_hh, p_gh, 3 * HH, HH);

    // 8. GRU nonlinearity -> h_new (also writes hidden output)
    hnew_kernel<<<(BB * HH) / 256, 256>>>(hidden, out_hidden);

    // 9. prediction = h_new @ out_w^T + out_b
    small_gemm<<<(VV + 63) / 64, 256>>>(p_hnew, HH, out_w, HH, out_b, out_pred, VV, HH);
}

// round 10
// speedup vs baseline: 2.6031x; 2.6031x over previous
#include <cuda_runtime.h>
#include <cuda_bf16.h>
#include <math.h>
#include <stdint.h>

#define BB 64
#define SS 512
#define HH 1024
#define VV 50257
#define BS (BB * SS)
#define RS 80   // smem row pitch bytes (32 bf16 = 64B data + 16B pad; conflict-free ldmatrix)

// ======================= scratch (device globals) ===========================
__device__ float g_p[BB * HH];
__device__ float g_scores[BB * SS];
__device__ float g_context[BB * HH];
__device__ float g_x[BB * 2 * HH];
__device__ float g_gi[BB * 3 * HH];
__device__ float g_gh[BB * 3 * HH];
__device__ float g_hnew[BB * HH];

// ======================= helpers ===========================================
__device__ __forceinline__ uint32_t smem_u32(const void* p) {
    uint32_t a;
    asm("{ .reg .u64 t; cvta.to.shared.u64 t, %1; cvt.u32.u64 %0, t; }"
        : "=r"(a) : "l"(p));
    return a;
}
__device__ __forceinline__ void ldsm4(uint32_t addr, uint32_t r[4]) {
    asm volatile("ldmatrix.sync.aligned.m8n8.x4.shared.b16 {%0,%1,%2,%3}, [%4];"
                 : "=r"(r[0]), "=r"(r[1]), "=r"(r[2]), "=r"(r[3]) : "r"(addr));
}
__device__ __forceinline__ void mma_bf16(float* c, const uint32_t* a, const uint32_t* b) {
    asm volatile(
        "mma.sync.aligned.m16n8k16.row.col.f32.bf16.bf16.f32 "
        "{%0,%1,%2,%3}, {%4,%5,%6,%7}, {%8,%9}, {%0,%1,%2,%3};"
        : "+f"(c[0]), "+f"(c[1]), "+f"(c[2]), "+f"(c[3])
        : "r"(a[0]), "r"(a[1]), "r"(a[2]), "r"(a[3]), "r"(b[0]), "r"(b[1]));
}
__device__ __forceinline__ uint32_t packbf(float a, float b) {
    union { __nv_bfloat162 v; uint32_t u; } t;
    t.v.x = __float2bfloat16(a);
    t.v.y = __float2bfloat16(b);
    return t.u;
}
// split a float4 into hi/lo bf16x2 pairs
__device__ __forceinline__ void split4(float4 v, uint2& hi, uint2& lo) {
    __nv_bfloat16 h0 = __float2bfloat16(v.x), h1 = __float2bfloat16(v.y);
    __nv_bfloat16 h2 = __float2bfloat16(v.z), h3 = __float2bfloat16(v.w);
    union { __nv_bfloat162 v2[2]; uint2 u; } H;
    H.v2[0].x = h0; H.v2[0].y = h1; H.v2[1].x = h2; H.v2[1].y = h3;
    hi = H.u;
    lo.x = packbf(v.x - __bfloat162float(h0), v.y - __bfloat162float(h1));
    lo.y = packbf(v.z - __bfloat162float(h2), v.w - __bfloat162float(h3));
}
__device__ __forceinline__ float tanha(float x) {
    float e = __expf(2.f * x);
    return 1.f - __fdividef(2.f, e + 1.f);
}

// ======================= zero scores =======================================
__global__ void zero_scores_kernel() {
    int i = blockIdx.x * 256 + threadIdx.x;
    if (i < BB * SS) g_scores[i] = 0.f;
}

// ======================= energy GEMM (mma.sync, split-bf16) ================
// scores[b,s] += sum_{n in tile} v[n]*tanh( p[b,n] + sum_k enc[b,s,k]*W2[n,k] )
// CTA tile 128(rows=B*S) x 128(n=h), KC=32, 8 warps (warp tile 32x64).
__global__ void __launch_bounds__(256)
attn_energy_mma(const float* __restrict__ enc,
                const float* __restrict__ attn_w,
                const float* __restrict__ v_w) {
    __shared__ char sm[4 * 128 * RS];          // Ahi, Alo, Bhi, Blo
    __shared__ float psh[128], vsh[128];
    __shared__ float red[128][2];

    const int tid = threadIdx.x, lane = tid & 31, wid = tid >> 5;
    const int n0 = blockIdx.x * 128;
    const int r0 = blockIdx.y * 128;
    const int b  = blockIdx.y >> 2;            // 128 rows | 512 per batch
    const int wm = wid >> 1, wn = wid & 1;

    if (tid < 128) {
        psh[tid] = g_p[b * HH + n0 + tid];
        vsh[tid] = v_w[n0 + tid];
    }

    char* smA  = sm;
    char* smAl = sm + 128 * RS;
    char* smB  = sm + 2 * 128 * RS;
    char* smBl = sm + 3 * 128 * RS;
    const uint32_t uA  = smem_u32(smA);
    const uint32_t uAl = uA + 128 * RS;
    const uint32_t uB  = uA + 2 * 128 * RS;
    const uint32_t uBl = uA + 3 * 128 * RS;

    const float* Ab = enc + (size_t)r0 * HH;
    const float* Bb = attn_w + (size_t)n0 * (2 * HH) + HH;

    float4 pf[8];
#pragma unroll
    for (int t = 0; t < 8; t++) {
        int id = t * 256 + tid;
        int row = (id >> 3) & 127, kf4 = id & 7;
        const float* p = (id < 1024) ? (Ab + (size_t)row * HH + kf4 * 4)
                                     : (Bb + (size_t)row * (2 * HH) + kf4 * 4);
        pf[t] = *(const float4*)p;
    }

    float acc[2][8][4];
#pragma unroll
    for (int i = 0; i < 2; i++)
#pragma unroll
        for (int j = 0; j < 8; j++)
#pragma unroll
            for (int q = 0; q < 4; q++) acc[i][j][q] = 0.f;

    for (int s = 0; s < 32; s++) {
        __syncthreads();
#pragma unroll
        for (int t = 0; t < 8; t++) {
            int id = t * 256 + tid;
            int row = (id >> 3) & 127, kf4 = id & 7;
            char* hi = (id < 1024) ? smA : smB;
            char* lo = (id < 1024) ? smAl : smBl;
            uint2 h, l;
            split4(pf[t], h, l);
            int off = row * RS + kf4 * 8;
            *(uint2*)(hi + off) = h;
            *(uint2*)(lo + off) = l;
        }
        __syncthreads();
        if (s < 31) {
            int k0 = (s + 1) * 32;
#pragma unroll
            for (int t = 0; t < 8; t++) {
                int id = t * 256 + tid;
                int row = (id >> 3) & 127, kf4 = id & 7;
                const float* p = (id < 1024)
                    ? (Ab + (size_t)row * HH + k0 + kf4 * 4)
                    : (Bb + (size_t)row * (2 * HH) + k0 + kf4 * 4);
                pf[t] = *(const float4*)p;
            }
        }
#pragma unroll
        for (int ks = 0; ks < 2; ks++) {
            uint32_t ah[2][4], al[2][4];
#pragma unroll
            for (int mf = 0; mf < 2; mf++) {
                int row = wm * 32 + mf * 16 + (lane & 7) + ((lane >> 3) & 1) * 8;
                int kb  = ks * 32 + ((lane >> 4) & 1) * 16;
                ldsm4(uA  + row * RS + kb, ah[mf]);
                ldsm4(uAl + row * RS + kb, al[mf]);
            }
            uint32_t bh[8][2], bl[8][2];
#pragma unroll
            for (int np = 0; np < 4; np++) {
                int row = wn * 64 + np * 16 + ((lane >> 4) & 1) * 8 + (lane & 7);
                int kb  = ks * 32 + ((lane >> 3) & 1) * 16;
                uint32_t r4[4];
                ldsm4(uB + row * RS + kb, r4);
                bh[2*np][0] = r4[0]; bh[2*np][1] = r4[1];
                bh[2*np+1][0] = r4[2]; bh[2*np+1][1] = r4[3];
                ldsm4(uBl + row * RS + kb, r4);
                bl[2*np][0] = r4[0]; bl[2*np][1] = r4[1];
                bl[2*np+1][0] = r4[2]; bl[2*np+1][1] = r4[3];
            }
#pragma unroll
            for (int mf = 0; mf < 2; mf++)
#pragma unroll
                for (int nf = 0; nf < 8; nf++) {
                    mma_bf16(acc[mf][nf], ah[mf], bh[nf]);
                    mma_bf16(acc[mf][nf], ah[mf], bl[nf]);
                    mma_bf16(acc[mf][nf], al[mf], bh[nf]);
                }
        }
    }

    // epilogue: tanh + v-weighted reduction over n
    __syncthreads();
    float sum[2][2] = {{0.f, 0.f}, {0.f, 0.f}};
#pragma unroll
    for (int mf = 0; mf < 2; mf++)
#pragma unroll
        for (int nf = 0; nf < 8; nf++) {
            int n = wn * 64 + nf * 8 + (lane & 3) * 2;
            float v0 = vsh[n], v1 = vsh[n + 1];
            float p0 = psh[n], p1 = psh[n + 1];
            sum[mf][0] += v0 * tanha(acc[mf][nf][0] + p0)
                        + v1 * tanha(acc[mf][nf][1] + p1);
            sum[mf][1] += v0 * tanha(acc[mf][nf][2] + p0)
                        + v1 * tanha(acc[mf][nf][3] + p1);
        }
#pragma unroll
    for (int mf = 0; mf < 2; mf++)
#pragma unroll
        for (int half = 0; half < 2; half++) {
            float sv = sum[mf][half];
            sv += __shfl_xor_sync(0xFFFFFFFF, sv, 1);
            sv += __shfl_xor_sync(0xFFFFFFFF, sv, 2);
            if ((lane & 3) == 0) {
                int r = wm * 32 + mf * 16 + half * 8 + (lane >> 2);
                red[r][wn] = sv;
            }
        }
    __syncthreads();
    if (tid < 128)
        atomicAdd(&g_scores[r0 + tid], red[tid][0] + red[tid][1]);
}

// ======================= generic M=64 GEMM (mma.sync, split-bf16) ==========
// C[64,N] = bias[n] + A[64,K] @ B[N,K]^T ;  CTA tile 64x128, warp tile 32x32.
__global__ void __launch_bounds__(256)
gemm64_mma(const float* __restrict__ A, int lda,
           const float* __restrict__ Bw, int ldb, int boff,
           const float* __restrict__ bias,
           float* __restrict__ C, int N, int K) {
    __shared__ char sm[2 * 64 * RS + 2 * 128 * RS];   // Ahi,Alo,Bhi,Blo

    const int tid = threadIdx.x, lane = tid & 31, wid = tid >> 5;
    const int n0 = blockIdx.x * 128;
    const int wm = wid & 1, wn = wid >> 1;

    char* smA  = sm;
    char* smAl = sm + 64 * RS;
    char* smB  = sm + 2 * 64 * RS;
    char* smBl = sm + 2 * 64 * RS + 128 * RS;
    const uint32_t uA  = smem_u32(smA);
    const uint32_t uAl = uA + 64 * RS;
    const uint32_t uB  = uA + 2 * 64 * RS;
    const uint32_t uBl = uB + 128 * RS;

    float4 pf[6];
#pragma unroll
    for (int t = 0; t < 6; t++) {
        int id = t * 256 + tid;
        if (id < 512) {
            int row = id >> 3, kf4 = id & 7;
            pf[t] = *(const float4*)(A + (size_t)row * lda + kf4 * 4);
        } else {
            int id2 = id - 512;
            int row = id2 >> 3, kf4 = id2 & 7;
            int rg = n0 + row;
            pf[t] = (rg < N)
                ? *(const float4*)(Bw + (size_t)rg * ldb + boff + kf4 * 4)
                : make_float4(0.f, 0.f, 0.f, 0.f);
        }
    }

    float acc[2][4][4];
#pragma unroll
    for (int i = 0; i < 2; i++)
#pragma unroll
        for (int j = 0; j < 4; j++)
#pragma unroll
            for (int q = 0; q < 4; q++) acc[i][j][q] = 0.f;

    const int nstages = K / 32;
    for (int s = 0; s < nstages; s++) {
        __syncthreads();
#pragma unroll
        for (int t = 0; t < 6; t++) {
            int id = t * 256 + tid;
            char *hi, *lo;
            int row, kf4;
            if (id < 512) { row = id >> 3; kf4 = id & 7; hi = smA; lo = smAl; }
            else { int id2 = id - 512; row = id2 >> 3; kf4 = id2 & 7; hi = smB; lo = smBl; }
            uint2 h, l;
            split4(pf[t], h, l);
            int off = row * RS + kf4 * 8;
            *(uint2*)(hi + off) = h;
            *(uint2*)(lo + off) = l;
        }
        __syncthreads();
        if (s < nstages - 1) {
            int k0 = (s + 1) * 32;
#pragma unroll
            for (int t = 0; t < 6; t++) {
                int id = t * 256 + tid;
                if (id < 512) {
                    int row = id >> 3, kf4 = id & 7;
                    pf[t] = *(const float4*)(A + (size_t)row * lda + k0 + kf4 * 4);
                } else {
                    int id2 = id - 512;
                    int row = id2 >> 3, kf4 = id2 & 7;
                    int rg = n0 + row;
                    pf[t] = (rg < N)
                        ? *(const float4*)(Bw + (size_t)rg * ldb + boff + k0 + kf4 * 4)
                        : make_float4(0.f, 0.f, 0.f, 0.f);
                }
            }
        }
#pragma unroll
        for (int ks = 0; ks < 2; ks++) {
            uint32_t ah[2][4], al[2][4];
#pragma unroll
            for (int mf = 0; mf < 2; mf++) {
                int row = wm * 32 + mf * 16 + (lane & 7) + ((lane >> 3) & 1) * 8;
                int kb  = ks * 32 + ((lane >> 4) & 1) * 16;
                ldsm4(uA  + row * RS + kb, ah[mf]);
                ldsm4(uAl + row * RS + kb, al[mf]);
            }
            uint32_t bh[4][2], bl[4][2];
#pragma unroll
            for (int np = 0; np < 2; np++) {
                int row = wn * 32 + np * 16 + ((lane >> 4) & 1) * 8 + (lane & 7);
                int kb  = ks * 32 + ((lane >> 3) & 1) * 16;
                uint32_t r4[4];
                ldsm4(uB + row * RS + kb, r4);
                bh[2*np][0] = r4[0]; bh[2*np][1] = r4[1];
                bh[2*np+1][0] = r4[2]; bh[2*np+1][1] = r4[3];
                ldsm4(uBl + row * RS + kb, r4);
                bl[2*np][0] = r4[0]; bl[2*np][1] = r4[1];
                bl[2*np+1][0] = r4[2]; bl[2*np+1][1] = r4[3];
            }
#pragma unroll
            for (int mf = 0; mf < 2; mf++)
#pragma unroll
                for (int nf = 0; nf < 4; nf++) {
                    mma_bf16(acc[mf][nf], ah[mf], bh[nf]);
                    mma_bf16(acc[mf][nf], ah[mf], bl[nf]);
                    mma_bf16(acc[mf][nf], al[mf], bh[nf]);
                }
        }
    }

    // epilogue: C = acc + bias (guarded for N edge)
#pragma unroll
    for (int mf = 0; mf < 2; mf++) {
        int m = wm * 32 + mf * 16 + (lane >> 2);
#pragma unroll
        for (int nf = 0; nf < 4; nf++) {
            int n = n0 + wn * 32 + nf * 8 + (lane & 3) * 2;
            if (n < N) {
                float bb0 = bias[n];
                C[(size_t)m * N + n]       = acc[mf][nf][0] + bb0;
                C[(size_t)(m + 8) * N + n] = acc[mf][nf][2] + bb0;
            }
            if (n + 1 < N) {
                float bb1 = bias[n + 1];
                C[(size_t)m * N + n + 1]       = acc[mf][nf][1] + bb1;
                C[(size_t)(m + 8) * N + n + 1] = acc[mf][nf][3] + bb1;
            }
        }
    }
}

// ======================= softmax ===========================================
__global__ void softmax_kernel(float* __restrict__ attn_out) {
    int b = blockIdx.x;
    int tid = threadIdx.x;
    __shared__ float sh[256];
    float v0 = g_scores[b * SS + tid];
    float v1 = g_scores[b * SS + 256 + tid];
    float m = fmaxf(v0, v1);
    sh[tid] = m;
    __syncthreads();
    for (int o = 128; o > 0; o >>= 1) {
        if (tid < o) sh[tid] = fmaxf(sh[tid], sh[tid + o]);
        __syncthreads();
    }
    m = sh[0];
    __syncthreads();
    float e0 = expf(v0 - m), e1 = expf(v1 - m);
    sh[tid] = e0 + e1;
    __syncthreads();
    for (int o = 128; o > 0; o >>= 1) {
        if (tid < o) sh[tid] += sh[tid + o];
        __syncthreads();
    }
    float inv = 1.f / sh[0];
    attn_out[b * SS + tid]       = e0 * inv;
    attn_out[b * SS + 256 + tid] = e1 * inv;
}

// ======================= context ===========================================
__global__ void context_kernel(const float* __restrict__ enc,
                               const float* __restrict__ attn) {
    int b = blockIdx.x;
    int h = blockIdx.y * 128 + threadIdx.x;
    __shared__ float ash[SS];
    for (int i = threadIdx.x; i < SS; i += 128) ash[i] = attn[b * SS + i];
    __syncthreads();
    const float* ep = enc + (size_t)b * SS * HH + h;
    float acc = 0.f;
#pragma unroll 4
    for (int s = 0; s < SS; s++) acc += ash[s] * ep[(size_t)s * HH];
    g_context[b * HH + h] = acc;
}

// ======================= x = [emb ; context] ================================
__global__ void xbuild_kernel(const int* __restrict__ ids,
                              const float* __restrict__ emb) {
    int idx = blockIdx.x * 256 + threadIdx.x;
    int b = idx >> 11, k = idx & 2047;
    float v;
    if (k < HH) v = emb[(size_t)ids[b] * HH + k];
    else        v = g_context[b * HH + (k - HH)];
    g_x[idx] = v;
}

// ======================= GRU elementwise ====================================
__global__ void hnew_kernel(const float* __restrict__ hidden,
                            float* __restrict__ out_hidden) {
    int idx = blockIdx.x * 256 + threadIdx.x;
    int b = idx >> 10, h = idx & 1023;
    int base = b * 3 * HH;
    float ir  = g_gi[base + h];
    float iz  = g_gi[base + HH + h];
    float in_ = g_gi[base + 2 * HH + h];
    float hr  = g_gh[base + h];
    float hz  = g_gh[base + HH + h];
    float hn  = g_gh[base + 2 * HH + h];
    float r = 1.f / (1.f + expf(-(ir + hr)));
    float z = 1.f / (1.f + expf(-(iz + hz)));
    float n = tanhf(in_ + r * hn);
    float ho = hidden[idx];
    float hv = (1.f - z) * n + z * ho;
    g_hnew[idx] = hv;
    out_hidden[idx] = hv;
}

// ======================= launch =============================================
extern "C" void kernel_launch(void* const* d_in, const int* in_sizes, int n_in,
                              void* d_out, int out_size) {
    const int*   ids    = (const int*)d_in[0];
    const float* hidden = (const float*)d_in[1];
    const float* enc    = (const float*)d_in[2];
    const float* emb    = (const float*)d_in[3];
    const float* attn_w = (const float*)d_in[4];
    const float* attn_b = (const float*)d_in[5];
    const float* v_w    = (const float*)d_in[6];
    const float* w_ih   = (const float*)d_in[7];
    const float* w_hh   = (const float*)d_in[8];
    const float* b_ih   = (const float*)d_in[9];
    const float* b_hh   = (const float*)d_in[10];
    const float* out_w  = (const float*)d_in[11];
    const float* out_b  = (const float*)d_in[12];

    float* out = (float*)d_out;
    float* out_pred   = out;
    float* out_hidden = out + (size_t)BB * VV;
    float* out_attn   = out_hidden + (size_t)BB * HH;

    float *p_p, *p_x, *p_gi, *p_gh, *p_hnew;
    cudaGetSymbolAddress((void**)&p_p,    g_p);
    cudaGetSymbolAddress((void**)&p_x,    g_x);
    cudaGetSymbolAddress((void**)&p_gi,   g_gi);
    cudaGetSymbolAddress((void**)&p_gh,   g_gh);
    cudaGetSymbolAddress((void**)&p_hnew, g_hnew);

    // 1. zero score accumulators
    zero_scores_kernel<<<(BB * SS) / 256, 256>>>();

    // 2. p = hidden @ W1^T + attn_b   (W1 = attn_w[:, :H])
    gemm64_mma<<<HH / 128, 256>>>(hidden, HH, attn_w, 2 * HH, 0, attn_b,
                                  p_p, HH, HH);

    // 3. energy GEMM + fused tanh/v reduction -> scores
    attn_energy_mma<<<dim3(HH / 128, BS / 128), 256>>>(enc, attn_w, v_w);

    // 4. softmax -> attn output
    softmax_kernel<<<BB, 256>>>(out_attn);

    // 5. context = attn @ enc
    context_kernel<<<dim3(BB, HH / 128), 128>>>(enc, out_attn);

    // 6. x = [embedded ; context]
    xbuild_kernel<<<(BB * 2 * HH) / 256, 256>>>(ids, emb);

    // 7. GRU gate GEMMs
    gemm64_mma<<<(3 * HH) / 128, 256>>>(p_x, 2 * HH, w_ih, 2 * HH, 0, b_ih,
                                        p_gi, 3 * HH, 2 * HH);
    gemm64_mma<<<(3 * HH) / 128, 256>>>(hidden, HH, w_hh, HH, 0, b_hh,
                                        p_gh, 3 * HH, HH);

    // 8. GRU nonlinearity -> h_new (also writes hidden output)
    hnew_kernel<<<(BB * HH) / 256, 256>>>(hidden, out_hidden);

    // 9. prediction = h_new @ out_w^T + out_b
    gemm64_mma<<<(VV + 127) / 128, 256>>>(p_hnew, HH, out_w, HH, 0, out_b,
                                          out_pred, VV, HH);
}

// round 11
// speedup vs baseline: 4.1459x; 1.5927x over previous
#include <cuda_runtime.h>
#include <cuda_bf16.h>
#include <cuda_fp16.h>
#include <math.h>
#include <stdint.h>

#define BB 64
#define SS 512
#define HH 1024
#define VV 50257
#define BS (BB * SS)
#define RS 80   // smem row pitch bytes (32 x 2B elems = 64B data + 16B pad)

// ======================= scratch (device globals) ===========================
__device__ float g_p[BB * HH];
__device__ float g_scores[BB * SS];
__device__ float g_context[BB * HH];
__device__ float g_x[BB * 2 * HH];
__device__ float g_gi[BB * 3 * HH];
__device__ float g_gh[BB * 3 * HH];
__device__ float g_hnew[BB * HH];
__device__ __half g_enc_h[BS * HH];     // fp16 copy of encoder_outputs
__device__ __half g_w2_h[HH * HH];      // fp16 copy of attn_w[:, H:2H]

// ======================= helpers ===========================================
__device__ __forceinline__ uint32_t smem_u32(const void* p) {
    uint32_t a;
    asm("{ .reg .u64 t; cvta.to.shared.u64 t, %1; cvt.u32.u64 %0, t; }"
        : "=r"(a) : "l"(p));
    return a;
}
__device__ __forceinline__ void ldsm4(uint32_t addr, uint32_t r[4]) {
    asm volatile("ldmatrix.sync.aligned.m8n8.x4.shared.b16 {%0,%1,%2,%3}, [%4];"
                 : "=r"(r[0]), "=r"(r[1]), "=r"(r[2]), "=r"(r[3]) : "r"(addr));
}
__device__ __forceinline__ void mma_bf16(float* c, const uint32_t* a, const uint32_t* b) {
    asm volatile(
        "mma.sync.aligned.m16n8k16.row.col.f32.bf16.bf16.f32 "
        "{%0,%1,%2,%3}, {%4,%5,%6,%7}, {%8,%9}, {%0,%1,%2,%3};"
        : "+f"(c[0]), "+f"(c[1]), "+f"(c[2]), "+f"(c[3])
        : "r"(a[0]), "r"(a[1]), "r"(a[2]), "r"(a[3]), "r"(b[0]), "r"(b[1]));
}
__device__ __forceinline__ void mma_f16(float* c, const uint32_t* a, const uint32_t* b) {
    asm volatile(
        "mma.sync.aligned.m16n8k16.row.col.f32.f16.f16.f32 "
        "{%0,%1,%2,%3}, {%4,%5,%6,%7}, {%8,%9}, {%0,%1,%2,%3};"
        : "+f"(c[0]), "+f"(c[1]), "+f"(c[2]), "+f"(c[3])
        : "r"(a[0]), "r"(a[1]), "r"(a[2]), "r"(a[3]), "r"(b[0]), "r"(b[1]));
}
__device__ __forceinline__ uint32_t packbf(float a, float b) {
    union { __nv_bfloat162 v; uint32_t u; } t;
    t.v.x = __float2bfloat16(a);
    t.v.y = __float2bfloat16(b);
    return t.u;
}
__device__ __forceinline__ void split4(float4 v, uint2& hi, uint2& lo) {
    __nv_bfloat16 h0 = __float2bfloat16(v.x), h1 = __float2bfloat16(v.y);
    __nv_bfloat16 h2 = __float2bfloat16(v.z), h3 = __float2bfloat16(v.w);
    union { __nv_bfloat162 v2[2]; uint2 u; } H;
    H.v2[0].x = h0; H.v2[0].y = h1; H.v2[1].x = h2; H.v2[1].y = h3;
    hi = H.u;
    lo.x = packbf(v.x - __bfloat162float(h0), v.y - __bfloat162float(h1));
    lo.y = packbf(v.z - __bfloat162float(h2), v.w - __bfloat162float(h3));
}
__device__ __forceinline__ float tanha(float x) {
    float e = __expf(2.f * x);
    return 1.f - __fdividef(2.f, e + 1.f);
}

// ======================= fp16 conversion kernels ===========================
__global__ void conv_enc_kernel(const float* __restrict__ enc) {
    size_t i = ((size_t)blockIdx.x * 256 + threadIdx.x) * 8;
    float4 a = *(const float4*)(enc + i);
    float4 b = *(const float4*)(enc + i + 4);
    union { __half2 h[4]; uint4 u; } P;
    P.h[0] = __floats2half2_rn(a.x, a.y);
    P.h[1] = __floats2half2_rn(a.z, a.w);
    P.h[2] = __floats2half2_rn(b.x, b.y);
    P.h[3] = __floats2half2_rn(b.z, b.w);
    *(uint4*)(g_enc_h + i) = P.u;
}
__global__ void conv_w2_kernel(const float* __restrict__ attn_w) {
    size_t e = ((size_t)blockIdx.x * 256 + threadIdx.x) * 8;
    int h = (int)(e >> 10), k = (int)(e & 1023);
    const float* src = attn_w + (size_t)h * (2 * HH) + HH + k;
    float4 a = *(const float4*)src;
    float4 b = *(const float4*)(src + 4);
    union { __half2 h2[4]; uint4 u; } P;
    P.h2[0] = __floats2half2_rn(a.x, a.y);
    P.h2[1] = __floats2half2_rn(a.z, a.w);
    P.h2[2] = __floats2half2_rn(b.x, b.y);
    P.h2[3] = __floats2half2_rn(b.z, b.w);
    *(uint4*)(g_w2_h + e) = P.u;
}

// ======================= zero scores =======================================
__global__ void zero_scores_kernel() {
    int i = blockIdx.x * 256 + threadIdx.x;
    if (i < BB * SS) g_scores[i] = 0.f;
}

// ======================= energy GEMM (fp16 single-product) =================
// scores[b,s] += sum_{n in tile} v[n]*tanh( p[b,n] + sum_k enc[b,s,k]*W2[n,k] )
// CTA tile 128(rows) x 128(n), KC=32, 8 warps (warp tile 32x64). fp16 inputs.
__global__ void __launch_bounds__(256)
attn_energy_h(const __half* __restrict__ E,
              const __half* __restrict__ W,
              const float* __restrict__ v_w) {
    __shared__ __align__(16) char sm[2 * 128 * RS];   // A, B fp16 tiles
    __shared__ float psh[128], vsh[128];
    __shared__ float red[128][2];

    const int tid = threadIdx.x, lane = tid & 31, wid = tid >> 5;
    const int n0 = blockIdx.x * 128;
    const int r0 = blockIdx.y * 128;
    const int b  = blockIdx.y >> 2;
    const int wm = wid >> 1, wn = wid & 1;

    if (tid < 128) {
        psh[tid] = g_p[b * HH + n0 + tid];
        vsh[tid] = v_w[n0 + tid];
    }

    char* smA = sm;
    char* smB = sm + 128 * RS;
    const uint32_t uA = smem_u32(smA);
    const uint32_t uB = uA + 128 * RS;

    const __half* Ab = E + (size_t)r0 * HH;
    const __half* Bb = W + (size_t)n0 * HH;

    // prefetch stage 0: 128 rows x 32 halves (64B = 4x16B segs) per matrix
    uint4 pf[4];
#pragma unroll
    for (int t = 0; t < 4; t++) {
        int id = t * 256 + tid;
        int row = (id >> 2) & 127, seg = id & 3;
        const __half* p = (id < 512) ? (Ab + (size_t)row * HH + seg * 8)
                                     : (Bb + (size_t)row * HH + seg * 8);
        pf[t] = *(const uint4*)p;
    }

    float acc[2][8][4];
#pragma unroll
    for (int i = 0; i < 2; i++)
#pragma unroll
        for (int j = 0; j < 8; j++)
#pragma unroll
            for (int q = 0; q < 4; q++) acc[i][j][q] = 0.f;

    for (int s = 0; s < 32; s++) {
        __syncthreads();
#pragma unroll
        for (int t = 0; t < 4; t++) {
            int id = t * 256 + tid;
            int row = (id >> 2) & 127, seg = id & 3;
            char* dst = (id < 512) ? smA : smB;
            *(uint4*)(dst + row * RS + seg * 16) = pf[t];
        }
        __syncthreads();
        if (s < 31) {
            int k0 = (s + 1) * 32;
#pragma unroll
            for (int t = 0; t < 4; t++) {
                int id = t * 256 + tid;
                int row = (id >> 2) & 127, seg = id & 3;
                const __half* p = (id < 512)
                    ? (Ab + (size_t)row * HH + k0 + seg * 8)
                    : (Bb + (size_t)row * HH + k0 + seg * 8);
                pf[t] = *(const uint4*)p;
            }
        }
#pragma unroll
        for (int ks = 0; ks < 2; ks++) {
            uint32_t ah[2][4];
#pragma unroll
            for (int mf = 0; mf < 2; mf++) {
                int row = wm * 32 + mf * 16 + (lane & 7) + ((lane >> 3) & 1) * 8;
                int kb  = ks * 32 + ((lane >> 4) & 1) * 16;
                ldsm4(uA + row * RS + kb, ah[mf]);
            }
            uint32_t bh[8][2];
#pragma unroll
            for (int np = 0; np < 4; np++) {
                int row = wn * 64 + np * 16 + ((lane >> 4) & 1) * 8 + (lane & 7);
                int kb  = ks * 32 + ((lane >> 3) & 1) * 16;
                uint32_t r4[4];
                ldsm4(uB + row * RS + kb, r4);
                bh[2*np][0] = r4[0]; bh[2*np][1] = r4[1];
                bh[2*np+1][0] = r4[2]; bh[2*np+1][1] = r4[3];
            }
#pragma unroll
            for (int mf = 0; mf < 2; mf++)
#pragma unroll
                for (int nf = 0; nf < 8; nf++)
                    mma_f16(acc[mf][nf], ah[mf], bh[nf]);
        }
    }

    // epilogue: tanh + v-weighted reduction over n
    __syncthreads();
    float sum[2][2] = {{0.f, 0.f}, {0.f, 0.f}};
#pragma unroll
    for (int mf = 0; mf < 2; mf++)
#pragma unroll
        for (int nf = 0; nf < 8; nf++) {
            int n = wn * 64 + nf * 8 + (lane & 3) * 2;
            float v0 = vsh[n], v1 = vsh[n + 1];
            float p0 = psh[n], p1 = psh[n + 1];
            sum[mf][0] += v0 * tanha(acc[mf][nf][0] + p0)
                        + v1 * tanha(acc[mf][nf][1] + p1);
            sum[mf][1] += v0 * tanha(acc[mf][nf][2] + p0)
                        + v1 * tanha(acc[mf][nf][3] + p1);
        }
#pragma unroll
    for (int mf = 0; mf < 2; mf++)
#pragma unroll
        for (int half = 0; half < 2; half++) {
            float sv = sum[mf][half];
            sv += __shfl_xor_sync(0xFFFFFFFF, sv, 1);
            sv += __shfl_xor_sync(0xFFFFFFFF, sv, 2);
            if ((lane & 3) == 0) {
                int r = wm * 32 + mf * 16 + half * 8 + (lane >> 2);
                red[r][wn] = sv;
            }
        }
    __syncthreads();
    if (tid < 128)
        atomicAdd(&g_scores[r0 + tid], red[tid][0] + red[tid][1]);
}

// ======================= generic M=64 GEMM (mma.sync, split-bf16) ==========
__global__ void __launch_bounds__(256)
gemm64_mma(const float* __restrict__ A, int lda,
           const float* __restrict__ Bw, int ldb, int boff,
           const float* __restrict__ bias,
           float* __restrict__ C, int N, int K) {
    __shared__ char sm[2 * 64 * RS + 2 * 128 * RS];   // Ahi,Alo,Bhi,Blo

    const int tid = threadIdx.x, lane = tid & 31, wid = tid >> 5;
    const int n0 = blockIdx.x * 128;
    const int wm = wid & 1, wn = wid >> 1;

    char* smA  = sm;
    char* smAl = sm + 64 * RS;
    char* smB  = sm + 2 * 64 * RS;
    char* smBl = sm + 2 * 64 * RS + 128 * RS;
    const uint32_t uA  = smem_u32(smA);
    const uint32_t uAl = uA + 64 * RS;
    const uint32_t uB  = uA + 2 * 64 * RS;
    const uint32_t uBl = uB + 128 * RS;

    float4 pf[6];
#pragma unroll
    for (int t = 0; t < 6; t++) {
        int id = t * 256 + tid;
        if (id < 512) {
            int row = id >> 3, kf4 = id & 7;
            pf[t] = *(const float4*)(A + (size_t)row * lda + kf4 * 4);
        } else {
            int id2 = id - 512;
            int row = id2 >> 3, kf4 = id2 & 7;
            int rg = n0 + row;
            pf[t] = (rg < N)
                ? *(const float4*)(Bw + (size_t)rg * ldb + boff + kf4 * 4)
                : make_float4(0.f, 0.f, 0.f, 0.f);
        }
    }

    float acc[2][4][4];
#pragma unroll
    for (int i = 0; i < 2; i++)
#pragma unroll
        for (int j = 0; j < 4; j++)
#pragma unroll
            for (int q = 0; q < 4; q++) acc[i][j][q] = 0.f;

    const int nstages = K / 32;
    for (int s = 0; s < nstages; s++) {
        __syncthreads();
#pragma unroll
        for (int t = 0; t < 6; t++) {
            int id = t * 256 + tid;
            char *hi, *lo;
            int row, kf4;
            if (id < 512) { row = id >> 3; kf4 = id & 7; hi = smA; lo = smAl; }
            else { int id2 = id - 512; row = id2 >> 3; kf4 = id2 & 7; hi = smB; lo = smBl; }
            uint2 h, l;
            split4(pf[t], h, l);
            int off = row * RS + kf4 * 8;
            *(uint2*)(hi + off) = h;
            *(uint2*)(lo + off) = l;
        }
        __syncthreads();
        if (s < nstages - 1) {
            int k0 = (s + 1) * 32;
#pragma unroll
            for (int t = 0; t < 6; t++) {
                int id = t * 256 + tid;
                if (id < 512) {
                    int row = id >> 3, kf4 = id & 7;
                    pf[t] = *(const float4*)(A + (size_t)row * lda + k0 + kf4 * 4);
                } else {
                    int id2 = id - 512;
                    int row = id2 >> 3, kf4 = id2 & 7;
                    int rg = n0 + row;
                    pf[t] = (rg < N)
                        ? *(const float4*)(Bw + (size_t)rg * ldb + boff + k0 + kf4 * 4)
                        : make_float4(0.f, 0.f, 0.f, 0.f);
                }
            }
        }
#pragma unroll
        for (int ks = 0; ks < 2; ks++) {
            uint32_t ah[2][4], al[2][4];
#pragma unroll
            for (int mf = 0; mf < 2; mf++) {
                int row = wm * 32 + mf * 16 + (lane & 7) + ((lane >> 3) & 1) * 8;
                int kb  = ks * 32 + ((lane >> 4) & 1) * 16;
                ldsm4(uA  + row * RS + kb, ah[mf]);
                ldsm4(uAl + row * RS + kb, al[mf]);
            }
            uint32_t bh[4][2], bl[4][2];
#pragma unroll
            for (int np = 0; np < 2; np++) {
                int row = wn * 32 + np * 16 + ((lane >> 4) & 1) * 8 + (lane & 7);
                int kb  = ks * 32 + ((lane >> 3) & 1) * 16;
                uint32_t r4[4];
                ldsm4(uB + row * RS + kb, r4);
                bh[2*np][0] = r4[0]; bh[2*np][1] = r4[1];
                bh[2*np+1][0] = r4[2]; bh[2*np+1][1] = r4[3];
                ldsm4(uBl + row * RS + kb, r4);
                bl[2*np][0] = r4[0]; bl[2*np][1] = r4[1];
                bl[2*np+1][0] = r4[2]; bl[2*np+1][1] = r4[3];
            }
#pragma unroll
            for (int mf = 0; mf < 2; mf++)
#pragma unroll
                for (int nf = 0; nf < 4; nf++) {
                    mma_bf16(acc[mf][nf], ah[mf], bh[nf]);
                    mma_bf16(acc[mf][nf], ah[mf], bl[nf]);
                    mma_bf16(acc[mf][nf], al[mf], bh[nf]);
                }
        }
    }

#pragma unroll
    for (int mf = 0; mf < 2; mf++) {
        int m = wm * 32 + mf * 16 + (lane >> 2);
#pragma unroll
        for (int nf = 0; nf < 4; nf++) {
            int n = n0 + wn * 32 + nf * 8 + (lane & 3) * 2;
            if (n < N) {
                float bb0 = bias[n];
                C[(size_t)m * N + n]       = acc[mf][nf][0] + bb0;
                C[(size_t)(m + 8) * N + n] = acc[mf][nf][2] + bb0;
            }
            if (n + 1 < N) {
                float bb1 = bias[n + 1];
                C[(size_t)m * N + n + 1]       = acc[mf][nf][1] + bb1;
                C[(size_t)(m + 8) * N + n + 1] = acc[mf][nf][3] + bb1;
            }
        }
    }
}

// ======================= softmax ===========================================
__global__ void softmax_kernel(float* __restrict__ attn_out) {
    int b = blockIdx.x;
    int tid = threadIdx.x;
    __shared__ float sh[256];
    float v0 = g_scores[b * SS + tid];
    float v1 = g_scores[b * SS + 256 + tid];
    float m = fmaxf(v0, v1);
    sh[tid] = m;
    __syncthreads();
    for (int o = 128; o > 0; o >>= 1) {
        if (tid < o) sh[tid] = fmaxf(sh[tid], sh[tid + o]);
        __syncthreads();
    }
    m = sh[0];
    __syncthreads();
    float e0 = expf(v0 - m), e1 = expf(v1 - m);
    sh[tid] = e0 + e1;
    __syncthreads();
    for (int o = 128; o > 0; o >>= 1) {
        if (tid < o) sh[tid] += sh[tid + o];
        __syncthreads();
    }
    float inv = 1.f / sh[0];
    attn_out[b * SS + tid]       = e0 * inv;
    attn_out[b * SS + 256 + tid] = e1 * inv;
}

// ======================= context ===========================================
__global__ void context_kernel(const float* __restrict__ enc,
                               const float* __restrict__ attn) {
    int b = blockIdx.x;
    int h = blockIdx.y * 128 + threadIdx.x;
    __shared__ float ash[SS];
    for (int i = threadIdx.x; i < SS; i += 128) ash[i] = attn[b * SS + i];
    __syncthreads();
    const float* ep = enc + (size_t)b * SS * HH + h;
    float acc = 0.f;
#pragma unroll 4
    for (int s = 0; s < SS; s++) acc += ash[s] * ep[(size_t)s * HH];
    g_context[b * HH + h] = acc;
}

// ======================= x = [emb ; context] ================================
__global__ void xbuild_kernel(const int* __restrict__ ids,
                              const float* __restrict__ emb) {
    int idx = blockIdx.x * 256 + threadIdx.x;
    int b = idx >> 11, k = idx & 2047;
    float v;
    if (k < HH) v = emb[(size_t)ids[b] * HH + k];
    else        v = g_context[b * HH + (k - HH)];
    g_x[idx] = v;
}

// ======================= GRU elementwise ====================================
__global__ void hnew_kernel(const float* __restrict__ hidden,
                            float* __restrict__ out_hidden) {
    int idx = blockIdx.x * 256 + threadIdx.x;
    int b = idx >> 10, h = idx & 1023;
    int base = b * 3 * HH;
    float ir  = g_gi[base + h];
    float iz  = g_gi[base + HH + h];
    float in_ = g_gi[base + 2 * HH + h];
    float hr  = g_gh[base + h];
    float hz  = g_gh[base + HH + h];
    float hn  = g_gh[base + 2 * HH + h];
    float r = 1.f / (1.f + expf(-(ir + hr)));
    float z = 1.f / (1.f + expf(-(iz + hz)));
    float n = tanhf(in_ + r * hn);
    float ho = hidden[idx];
    float hv = (1.f - z) * n + z * ho;
    g_hnew[idx] = hv;
    out_hidden[idx] = hv;
}

// ======================= launch =============================================
extern "C" void kernel_launch(void* const* d_in, const int* in_sizes, int n_in,
                              void* d_out, int out_size) {
    const int*   ids    = (const int*)d_in[0];
    const float* hidden = (const float*)d_in[1];
    const float* enc    = (const float*)d_in[2];
    const float* emb    = (const float*)d_in[3];
    const float* attn_w = (const float*)d_in[4];
    const float* attn_b = (const float*)d_in[5];
    const float* v_w    = (const float*)d_in[6];
    const float* w_ih   = (const float*)d_in[7];
    const float* w_hh   = (const float*)d_in[8];
    const float* b_ih   = (const float*)d_in[9];
    const float* b_hh   = (const float*)d_in[10];
    const float* out_w  = (const float*)d_in[11];
    const float* out_b  = (const float*)d_in[12];

    float* out = (float*)d_out;
    float* out_pred   = out;
    float* out_hidden = out + (size_t)BB * VV;
    float* out_attn   = out_hidden + (size_t)BB * HH;

    float *p_p, *p_x, *p_gi, *p_gh, *p_hnew;
    cudaGetSymbolAddress((void**)&p_p,    g_p);
    cudaGetSymbolAddress((void**)&p_x,    g_x);
    cudaGetSymbolAddress((void**)&p_gi,   g_gi);
    cudaGetSymbolAddress((void**)&p_gh,   g_gh);
    cudaGetSymbolAddress((void**)&p_hnew, g_hnew);
    __half *p_eh, *p_wh;
    cudaGetSymbolAddress((void**)&p_eh, g_enc_h);
    cudaGetSymbolAddress((void**)&p_wh, g_w2_h);

    // 1. fp16 conversions + zero scores
    conv_enc_kernel<<<(BS * HH) / 2048, 256>>>(enc);
    conv_w2_kernel<<<(HH * HH) / 2048, 256>>>(attn_w);
    zero_scores_kernel<<<(BB * SS) / 256, 256>>>();

    // 2. p = hidden @ W1^T + attn_b   (W1 = attn_w[:, :H])
    gemm64_mma<<<HH / 128, 256>>>(hidden, HH, attn_w, 2 * HH, 0, attn_b,
                                  p_p, HH, HH);

    // 3. energy GEMM (fp16) + fused tanh/v reduction -> scores
    attn_energy_h<<<dim3(HH / 128, BS / 128), 256>>>(p_eh, p_wh, v_w);

    // 4. softmax -> attn output
    softmax_kernel<<<BB, 256>>>(out_attn);

    // 5. context = attn @ enc
    context_kernel<<<dim3(BB, HH / 128), 128>>>(enc, out_attn);

    // 6. x = [embedded ; context]
    xbuild_kernel<<<(BB * 2 * HH) / 256, 256>>>(ids, emb);

    // 7. GRU gate GEMMs
    gemm64_mma<<<(3 * HH) / 128, 256>>>(p_x, 2 * HH, w_ih, 2 * HH, 0, b_ih,
                                        p_gi, 3 * HH, 2 * HH);
    gemm64_mma<<<(3 * HH) / 128, 256>>>(hidden, HH, w_hh, HH, 0, b_hh,
                                        p_gh, 3 * HH, HH);

    // 8. GRU nonlinearity -> h_new (also writes hidden output)
    hnew_kernel<<<(BB * HH) / 256, 256>>>(hidden, out_hidden);

    // 9. prediction = h_new @ out_w^T + out_b
    gemm64_mma<<<(VV + 127) / 128, 256>>>(p_hnew, HH, out_w, HH, 0, out_b,
                                          out_pred, VV, HH);
}

// round 12
// speedup vs baseline: 5.0818x; 1.2257x over previous
#include <cuda_runtime.h>
#include <cuda_bf16.h>
#include <cuda_fp16.h>
#include <math.h>
#include <stdint.h>

#define BB 64
#define SS 512
#define HH 1024
#define VV 50257
#define BS (BB * SS)
#define RS 80   // smem row pitch bytes (32 x 2B elems = 64B data + 16B pad)

// ======================= scratch (device globals) ===========================
__device__ float g_p[BB * HH];
__device__ float g_scores[BB * SS];
__device__ float g_context[BB * HH];
__device__ float g_x[BB * 2 * HH];
__device__ float g_gi[BB * 3 * HH];
__device__ float g_gh[BB * 3 * HH];
__device__ float g_hnew[BB * HH];
__device__ __half g_enc_h[BS * HH];     // fp16 copy of encoder_outputs
__device__ __half g_w2_h[HH * HH];      // fp16 copy of attn_w[:, H:2H]

// ======================= helpers ===========================================
__device__ __forceinline__ uint32_t smem_u32(const void* p) {
    uint32_t a;
    asm("{ .reg .u64 t; cvta.to.shared.u64 t, %1; cvt.u32.u64 %0, t; }"
        : "=r"(a) : "l"(p));
    return a;
}
__device__ __forceinline__ void ldsm4(uint32_t addr, uint32_t r[4]) {
    asm volatile("ldmatrix.sync.aligned.m8n8.x4.shared.b16 {%0,%1,%2,%3}, [%4];"
                 : "=r"(r[0]), "=r"(r[1]), "=r"(r[2]), "=r"(r[3]) : "r"(addr));
}
__device__ __forceinline__ void mma_bf16(float* c, const uint32_t* a, const uint32_t* b) {
    asm volatile(
        "mma.sync.aligned.m16n8k16.row.col.f32.bf16.bf16.f32 "
        "{%0,%1,%2,%3}, {%4,%5,%6,%7}, {%8,%9}, {%0,%1,%2,%3};"
        : "+f"(c[0]), "+f"(c[1]), "+f"(c[2]), "+f"(c[3])
        : "r"(a[0]), "r"(a[1]), "r"(a[2]), "r"(a[3]), "r"(b[0]), "r"(b[1]));
}
__device__ __forceinline__ void mma_f16(float* c, const uint32_t* a, const uint32_t* b) {
    asm volatile(
        "mma.sync.aligned.m16n8k16.row.col.f32.f16.f16.f32 "
        "{%0,%1,%2,%3}, {%4,%5,%6,%7}, {%8,%9}, {%0,%1,%2,%3};"
        : "+f"(c[0]), "+f"(c[1]), "+f"(c[2]), "+f"(c[3])
        : "r"(a[0]), "r"(a[1]), "r"(a[2]), "r"(a[3]), "r"(b[0]), "r"(b[1]));
}
__device__ __forceinline__ uint32_t packbf(float a, float b) {
    union { __nv_bfloat162 v; uint32_t u; } t;
    t.v.x = __float2bfloat16(a);
    t.v.y = __float2bfloat16(b);
    return t.u;
}
__device__ __forceinline__ void split4(float4 v, uint2& hi, uint2& lo) {
    __nv_bfloat16 h0 = __float2bfloat16(v.x), h1 = __float2bfloat16(v.y);
    __nv_bfloat16 h2 = __float2bfloat16(v.z), h3 = __float2bfloat16(v.w);
    union { __nv_bfloat162 v2[2]; uint2 u; } H;
    H.v2[0].x = h0; H.v2[0].y = h1; H.v2[1].x = h2; H.v2[1].y = h3;
    hi = H.u;
    lo.x = packbf(v.x - __bfloat162float(h0), v.y - __bfloat162float(h1));
    lo.y = packbf(v.z - __bfloat162float(h2), v.w - __bfloat162float(h3));
}
__device__ __forceinline__ float tanha(float x) {
    float e = __expf(2.f * x);
    return 1.f - __fdividef(2.f, e + 1.f);
}

// ======================= fp16 conversion kernels ===========================
__global__ void conv_enc_kernel(const float* __restrict__ enc) {
    size_t i = ((size_t)blockIdx.x * 256 + threadIdx.x) * 8;
    float4 a = *(const float4*)(enc + i);
    float4 b = *(const float4*)(enc + i + 4);
    union { __half2 h[4]; uint4 u; } P;
    P.h[0] = __floats2half2_rn(a.x, a.y);
    P.h[1] = __floats2half2_rn(a.z, a.w);
    P.h[2] = __floats2half2_rn(b.x, b.y);
    P.h[3] = __floats2half2_rn(b.z, b.w);
    *(uint4*)(g_enc_h + i) = P.u;
}
__global__ void conv_w2_kernel(const float* __restrict__ attn_w) {
    size_t e = ((size_t)blockIdx.x * 256 + threadIdx.x) * 8;
    int h = (int)(e >> 10), k = (int)(e & 1023);
    const float* src = attn_w + (size_t)h * (2 * HH) + HH + k;
    float4 a = *(const float4*)src;
    float4 b = *(const float4*)(src + 4);
    union { __half2 h2[4]; uint4 u; } P;
    P.h2[0] = __floats2half2_rn(a.x, a.y);
    P.h2[1] = __floats2half2_rn(a.z, a.w);
    P.h2[2] = __floats2half2_rn(b.x, b.y);
    P.h2[3] = __floats2half2_rn(b.z, b.w);
    *(uint4*)(g_w2_h + e) = P.u;
}

// ======================= zero scratch (scores + split-K accumulators) ======
__global__ void zero_scratch_kernel() {
    int i = blockIdx.x * 256 + threadIdx.x;
    if (i < BB * SS) g_scores[i] = 0.f;
    if (i < BB * HH) g_p[i] = 0.f;
    if (i < BB * 3 * HH) { g_gi[i] = 0.f; g_gh[i] = 0.f; }
}

// ======================= energy GEMM (fp16 single-product) =================
// scores[b,s] += sum_{n in tile} v[n]*tanh( p[b,n] + sum_k enc[b,s,k]*W2[n,k] )
// CTA tile 128(rows) x 128(n), KC=32, 8 warps (warp tile 32x64). fp16 inputs.
__global__ void __launch_bounds__(256)
attn_energy_h(const __half* __restrict__ E,
              const __half* __restrict__ W,
              const float* __restrict__ v_w) {
    __shared__ __align__(16) char sm[2 * 128 * RS];   // A, B fp16 tiles
    __shared__ float psh[128], vsh[128];
    __shared__ float red[128][2];

    const int tid = threadIdx.x, lane = tid & 31, wid = tid >> 5;
    const int n0 = blockIdx.x * 128;
    const int r0 = blockIdx.y * 128;
    const int b  = blockIdx.y >> 2;
    const int wm = wid >> 1, wn = wid & 1;

    if (tid < 128) {
        psh[tid] = g_p[b * HH + n0 + tid];
        vsh[tid] = v_w[n0 + tid];
    }

    char* smA = sm;
    char* smB = sm + 128 * RS;
    const uint32_t uA = smem_u32(smA);
    const uint32_t uB = uA + 128 * RS;

    const __half* Ab = E + (size_t)r0 * HH;
    const __half* Bb = W + (size_t)n0 * HH;

    uint4 pf[4];
#pragma unroll
    for (int t = 0; t < 4; t++) {
        int id = t * 256 + tid;
        int row = (id >> 2) & 127, seg = id & 3;
        const __half* p = (id < 512) ? (Ab + (size_t)row * HH + seg * 8)
                                     : (Bb + (size_t)row * HH + seg * 8);
        pf[t] = *(const uint4*)p;
    }

    float acc[2][8][4];
#pragma unroll
    for (int i = 0; i < 2; i++)
#pragma unroll
        for (int j = 0; j < 8; j++)
#pragma unroll
            for (int q = 0; q < 4; q++) acc[i][j][q] = 0.f;

    for (int s = 0; s < 32; s++) {
        __syncthreads();
#pragma unroll
        for (int t = 0; t < 4; t++) {
            int id = t * 256 + tid;
            int row = (id >> 2) & 127, seg = id & 3;
            char* dst = (id < 512) ? smA : smB;
            *(uint4*)(dst + row * RS + seg * 16) = pf[t];
        }
        __syncthreads();
        if (s < 31) {
            int k0 = (s + 1) * 32;
#pragma unroll
            for (int t = 0; t < 4; t++) {
                int id = t * 256 + tid;
                int row = (id >> 2) & 127, seg = id & 3;
                const __half* p = (id < 512)
                    ? (Ab + (size_t)row * HH + k0 + seg * 8)
                    : (Bb + (size_t)row * HH + k0 + seg * 8);
                pf[t] = *(const uint4*)p;
            }
        }
#pragma unroll
        for (int ks = 0; ks < 2; ks++) {
            uint32_t ah[2][4];
#pragma unroll
            for (int mf = 0; mf < 2; mf++) {
                int row = wm * 32 + mf * 16 + (lane & 7) + ((lane >> 3) & 1) * 8;
                int kb  = ks * 32 + ((lane >> 4) & 1) * 16;
                ldsm4(uA + row * RS + kb, ah[mf]);
            }
            uint32_t bh[8][2];
#pragma unroll
            for (int np = 0; np < 4; np++) {
                int row = wn * 64 + np * 16 + ((lane >> 4) & 1) * 8 + (lane & 7);
                int kb  = ks * 32 + ((lane >> 3) & 1) * 16;
                uint32_t r4[4];
                ldsm4(uB + row * RS + kb, r4);
                bh[2*np][0] = r4[0]; bh[2*np][1] = r4[1];
                bh[2*np+1][0] = r4[2]; bh[2*np+1][1] = r4[3];
            }
#pragma unroll
            for (int mf = 0; mf < 2; mf++)
#pragma unroll
                for (int nf = 0; nf < 8; nf++)
                    mma_f16(acc[mf][nf], ah[mf], bh[nf]);
        }
    }

    // epilogue: tanh + v-weighted reduction over n
    __syncthreads();
    float sum[2][2] = {{0.f, 0.f}, {0.f, 0.f}};
#pragma unroll
    for (int mf = 0; mf < 2; mf++)
#pragma unroll
        for (int nf = 0; nf < 8; nf++) {
            int n = wn * 64 + nf * 8 + (lane & 3) * 2;
            float v0 = vsh[n], v1 = vsh[n + 1];
            float p0 = psh[n], p1 = psh[n + 1];
            sum[mf][0] += v0 * tanha(acc[mf][nf][0] + p0)
                        + v1 * tanha(acc[mf][nf][1] + p1);
            sum[mf][1] += v0 * tanha(acc[mf][nf][2] + p0)
                        + v1 * tanha(acc[mf][nf][3] + p1);
        }
#pragma unroll
    for (int mf = 0; mf < 2; mf++)
#pragma unroll
        for (int half = 0; half < 2; half++) {
            float sv = sum[mf][half];
            sv += __shfl_xor_sync(0xFFFFFFFF, sv, 1);
            sv += __shfl_xor_sync(0xFFFFFFFF, sv, 2);
            if ((lane & 3) == 0) {
                int r = wm * 32 + mf * 16 + half * 8 + (lane >> 2);
                red[r][wn] = sv;
            }
        }
    __syncthreads();
    if (tid < 128)
        atomicAdd(&g_scores[r0 + tid], red[tid][0] + red[tid][1]);
}

// ======================= generic M=64 GEMM (mma.sync, split-bf16) ==========
// C[64,N] = bias + A[64,K] @ B[N,K]^T. grid.y = split-K slices (atomicAdd path,
// C pre-zeroed, bias added by slice 0). grid.y==1 -> direct store.
__global__ void __launch_bounds__(256)
gemm64_mma(const float* __restrict__ A, int lda,
           const float* __restrict__ Bw, int ldb, int boff,
           const float* __restrict__ bias,
           float* __restrict__ C, int N, int K) {
    __shared__ char sm[2 * 64 * RS + 2 * 128 * RS];   // Ahi,Alo,Bhi,Blo

    const int tid = threadIdx.x, lane = tid & 31, wid = tid >> 5;
    const int n0 = blockIdx.x * 128;
    const int wm = wid & 1, wn = wid >> 1;
    const int nk = K / gridDim.y;
    const int kbeg = blockIdx.y * nk;

    char* smA  = sm;
    char* smAl = sm + 64 * RS;
    char* smB  = sm + 2 * 64 * RS;
    char* smBl = sm + 2 * 64 * RS + 128 * RS;
    const uint32_t uA  = smem_u32(smA);
    const uint32_t uAl = uA + 64 * RS;
    const uint32_t uB  = uA + 2 * 64 * RS;
    const uint32_t uBl = uB + 128 * RS;

    float4 pf[6];
#pragma unroll
    for (int t = 0; t < 6; t++) {
        int id = t * 256 + tid;
        if (id < 512) {
            int row = id >> 3, kf4 = id & 7;
            pf[t] = *(const float4*)(A + (size_t)row * lda + kbeg + kf4 * 4);
        } else {
            int id2 = id - 512;
            int row = id2 >> 3, kf4 = id2 & 7;
            int rg = n0 + row;
            pf[t] = (rg < N)
                ? *(const float4*)(Bw + (size_t)rg * ldb + boff + kbeg + kf4 * 4)
                : make_float4(0.f, 0.f, 0.f, 0.f);
        }
    }

    float acc[2][4][4];
#pragma unroll
    for (int i = 0; i < 2; i++)
#pragma unroll
        for (int j = 0; j < 4; j++)
#pragma unroll
            for (int q = 0; q < 4; q++) acc[i][j][q] = 0.f;

    const int nstages = nk / 32;
    for (int s = 0; s < nstages; s++) {
        __syncthreads();
#pragma unroll
        for (int t = 0; t < 6; t++) {
            int id = t * 256 + tid;
            char *hi, *lo;
            int row, kf4;
            if (id < 512) { row = id >> 3; kf4 = id & 7; hi = smA; lo = smAl; }
            else { int id2 = id - 512; row = id2 >> 3; kf4 = id2 & 7; hi = smB; lo = smBl; }
            uint2 h, l;
            split4(pf[t], h, l);
            int off = row * RS + kf4 * 8;
            *(uint2*)(hi + off) = h;
            *(uint2*)(lo + off) = l;
        }
        __syncthreads();
        if (s < nstages - 1) {
            int k0 = kbeg + (s + 1) * 32;
#pragma unroll
            for (int t = 0; t < 6; t++) {
                int id = t * 256 + tid;
                if (id < 512) {
                    int row = id >> 3, kf4 = id & 7;
                    pf[t] = *(const float4*)(A + (size_t)row * lda + k0 + kf4 * 4);
                } else {
                    int id2 = id - 512;
                    int row = id2 >> 3, kf4 = id2 & 7;
                    int rg = n0 + row;
                    pf[t] = (rg < N)
                        ? *(const float4*)(Bw + (size_t)rg * ldb + boff + k0 + kf4 * 4)
                        : make_float4(0.f, 0.f, 0.f, 0.f);
                }
            }
        }
#pragma unroll
        for (int ks = 0; ks < 2; ks++) {
            uint32_t ah[2][4], al[2][4];
#pragma unroll
            for (int mf = 0; mf < 2; mf++) {
                int row = wm * 32 + mf * 16 + (lane & 7) + ((lane >> 3) & 1) * 8;
                int kb  = ks * 32 + ((lane >> 4) & 1) * 16;
                ldsm4(uA  + row * RS + kb, ah[mf]);
                ldsm4(uAl + row * RS + kb, al[mf]);
            }
            uint32_t bh[4][2], bl[4][2];
#pragma unroll
            for (int np = 0; np < 2; np++) {
                int row = wn * 32 + np * 16 + ((lane >> 4) & 1) * 8 + (lane & 7);
                int kb  = ks * 32 + ((lane >> 3) & 1) * 16;
                uint32_t r4[4];
                ldsm4(uB + row * RS + kb, r4);
                bh[2*np][0] = r4[0]; bh[2*np][1] = r4[1];
                bh[2*np+1][0] = r4[2]; bh[2*np+1][1] = r4[3];
                ldsm4(uBl + row * RS + kb, r4);
                bl[2*np][0] = r4[0]; bl[2*np][1] = r4[1];
                bl[2*np+1][0] = r4[2]; bl[2*np+1][1] = r4[3];
            }
#pragma unroll
            for (int mf = 0; mf < 2; mf++)
#pragma unroll
                for (int nf = 0; nf < 4; nf++) {
                    mma_bf16(acc[mf][nf], ah[mf], bh[nf]);
                    mma_bf16(acc[mf][nf], ah[mf], bl[nf]);
                    mma_bf16(acc[mf][nf], al[mf], bh[nf]);
                }
        }
    }

    const bool direct = (gridDim.y == 1);
    const bool addb = (blockIdx.y == 0);
#pragma unroll
    for (int mf = 0; mf < 2; mf++) {
        int m = wm * 32 + mf * 16 + (lane >> 2);
#pragma unroll
        for (int nf = 0; nf < 4; nf++) {
            int n = n0 + wn * 32 + nf * 8 + (lane & 3) * 2;
            if (n < N) {
                float bb0 = addb ? bias[n] : 0.f;
                if (direct) {
                    C[(size_t)m * N + n]       = acc[mf][nf][0] + bb0;
                    C[(size_t)(m + 8) * N + n] = acc[mf][nf][2] + bb0;
                } else {
                    atomicAdd(&C[(size_t)m * N + n],       acc[mf][nf][0] + bb0);
                    atomicAdd(&C[(size_t)(m + 8) * N + n], acc[mf][nf][2] + bb0);
                }
            }
            if (n + 1 < N) {
                float bb1 = addb ? bias[n + 1] : 0.f;
                if (direct) {
                    C[(size_t)m * N + n + 1]       = acc[mf][nf][1] + bb1;
                    C[(size_t)(m + 8) * N + n + 1] = acc[mf][nf][3] + bb1;
                } else {
                    atomicAdd(&C[(size_t)m * N + n + 1],       acc[mf][nf][1] + bb1);
                    atomicAdd(&C[(size_t)(m + 8) * N + n + 1], acc[mf][nf][3] + bb1);
                }
            }
        }
    }
}

// ======================= softmax ===========================================
__global__ void softmax_kernel(float* __restrict__ attn_out) {
    int b = blockIdx.x;
    int tid = threadIdx.x;
    __shared__ float sh[256];
    float v0 = g_scores[b * SS + tid];
    float v1 = g_scores[b * SS + 256 + tid];
    float m = fmaxf(v0, v1);
    sh[tid] = m;
    __syncthreads();
    for (int o = 128; o > 0; o >>= 1) {
        if (tid < o) sh[tid] = fmaxf(sh[tid], sh[tid + o]);
        __syncthreads();
    }
    m = sh[0];
    __syncthreads();
    float e0 = expf(v0 - m), e1 = expf(v1 - m);
    sh[tid] = e0 + e1;
    __syncthreads();
    for (int o = 128; o > 0; o >>= 1) {
        if (tid < o) sh[tid] += sh[tid + o];
        __syncthreads();
    }
    float inv = 1.f / sh[0];
    attn_out[b * SS + tid]       = e0 * inv;
    attn_out[b * SS + 256 + tid] = e1 * inv;
}

// ======================= context ===========================================
__global__ void context_kernel(const float* __restrict__ enc,
                               const float* __restrict__ attn) {
    int b = blockIdx.x;
    int h = blockIdx.y * 128 + threadIdx.x;
    __shared__ float ash[SS];
    for (int i = threadIdx.x; i < SS; i += 128) ash[i] = attn[b * SS + i];
    __syncthreads();
    const float* ep = enc + (size_t)b * SS * HH + h;
    float acc = 0.f;
#pragma unroll 4
    for (int s = 0; s < SS; s++) acc += ash[s] * ep[(size_t)s * HH];
    g_context[b * HH + h] = acc;
}

// ======================= x = [emb ; context] ================================
__global__ void xbuild_kernel(const int* __restrict__ ids,
                              const float* __restrict__ emb) {
    int idx = blockIdx.x * 256 + threadIdx.x;
    int b = idx >> 11, k = idx & 2047;
    float v;
    if (k < HH) v = emb[(size_t)ids[b] * HH + k];
    else        v = g_context[b * HH + (k - HH)];
    g_x[idx] = v;
}

// ======================= GRU elementwise ====================================
__global__ void hnew_kernel(const float* __restrict__ hidden,
                            float* __restrict__ out_hidden) {
    int idx = blockIdx.x * 256 + threadIdx.x;
    int b = idx >> 10, h = idx & 1023;
    int base = b * 3 * HH;
    float ir  = g_gi[base + h];
    float iz  = g_gi[base + HH + h];
    float in_ = g_gi[base + 2 * HH + h];
    float hr  = g_gh[base + h];
    float hz  = g_gh[base + HH + h];
    float hn  = g_gh[base + 2 * HH + h];
    float r = 1.f / (1.f + expf(-(ir + hr)));
    float z = 1.f / (1.f + expf(-(iz + hz)));
    float n = tanhf(in_ + r * hn);
    float ho = hidden[idx];
    float hv = (1.f - z) * n + z * ho;
    g_hnew[idx] = hv;
    out_hidden[idx] = hv;
}

// ======================= launch =============================================
extern "C" void kernel_launch(void* const* d_in, const int* in_sizes, int n_in,
                              void* d_out, int out_size) {
    const int*   ids    = (const int*)d_in[0];
    const float* hidden = (const float*)d_in[1];
    const float* enc    = (const float*)d_in[2];
    const float* emb    = (const float*)d_in[3];
    const float* attn_w = (const float*)d_in[4];
    const float* attn_b = (const float*)d_in[5];
    const float* v_w    = (const float*)d_in[6];
    const float* w_ih   = (const float*)d_in[7];
    const float* w_hh   = (const float*)d_in[8];
    const float* b_ih   = (const float*)d_in[9];
    const float* b_hh   = (const float*)d_in[10];
    const float* out_w  = (const float*)d_in[11];
    const float* out_b  = (const float*)d_in[12];

    float* out = (float*)d_out;
    float* out_pred   = out;
    float* out_hidden = out + (size_t)BB * VV;
    float* out_attn   = out_hidden + (size_t)BB * HH;

    float *p_p, *p_x, *p_gi, *p_gh, *p_hnew;
    cudaGetSymbolAddress((void**)&p_p,    g_p);
    cudaGetSymbolAddress((void**)&p_x,    g_x);
    cudaGetSymbolAddress((void**)&p_gi,   g_gi);
    cudaGetSymbolAddress((void**)&p_gh,   g_gh);
    cudaGetSymbolAddress((void**)&p_hnew, g_hnew);
    __half *p_eh, *p_wh;
    cudaGetSymbolAddress((void**)&p_eh, g_enc_h);
    cudaGetSymbolAddress((void**)&p_wh, g_w2_h);

    // 1. fp16 conversions + zero split-K accumulators / scores
    conv_enc_kernel<<<(BS * HH) / 2048, 256>>>(enc);
    conv_w2_kernel<<<(HH * HH) / 2048, 256>>>(attn_w);
    zero_scratch_kernel<<<(BB * 3 * HH) / 256, 256>>>();

    // 2. p = hidden @ W1^T + attn_b   (split-K 8)
    gemm64_mma<<<dim3(HH / 128, 8), 256>>>(hidden, HH, attn_w, 2 * HH, 0,
                                           attn_b, p_p, HH, HH);

    // 3. energy GEMM (fp16) + fused tanh/v reduction -> scores
    attn_energy_h<<<dim3(HH / 128, BS / 128), 256>>>(p_eh, p_wh, v_w);

    // 4. softmax -> attn output
    softmax_kernel<<<BB, 256>>>(out_attn);

    // 5. context = attn @ enc
    context_kernel<<<dim3(BB, HH / 128), 128>>>(enc, out_attn);

    // 6. x = [embedded ; context]
    xbuild_kernel<<<(BB * 2 * HH) / 256, 256>>>(ids, emb);

    // 7. GRU gate GEMMs (split-K 4)
    gemm64_mma<<<dim3((3 * HH) / 128, 4), 256>>>(p_x, 2 * HH, w_ih, 2 * HH, 0,
                                                 b_ih, p_gi, 3 * HH, 2 * HH);
    gemm64_mma<<<dim3((3 * HH) / 128, 4), 256>>>(hidden, HH, w_hh, HH, 0,
                                                 b_hh, p_gh, 3 * HH, HH);

    // 8. GRU nonlinearity -> h_new (also writes hidden output)
    hnew_kernel<<<(BB * HH) / 256, 256>>>(hidden, out_hidden);

    // 9. prediction = h_new @ out_w^T + out_b  (direct-store, BW-bound)
    gemm64_mma<<<dim3((VV + 127) / 128, 1), 256>>>(p_hnew, HH, out_w, HH, 0,
                                                   out_b, out_pred, VV, HH);
}

// round 13
// speedup vs baseline: 5.2812x; 1.0392x over previous
#include <cuda_runtime.h>
#include <cuda_fp16.h>
#include <math.h>
#include <stdint.h>

#define BB 64
#define SS 512
#define HH 1024
#define VV 50257
#define BS (BB * SS)
#define RS 80   // smem row pitch bytes (32 x 2B elems = 64B data + 16B pad)

// ======================= scratch (device globals) ===========================
__device__ float g_p[BB * HH];
__device__ float g_scores[BB * SS];
__device__ float g_context[BB * HH];
__device__ float g_x[BB * 2 * HH];
__device__ float g_gi[BB * 3 * HH];
__device__ float g_gh[BB * 3 * HH];
__device__ float g_hnew[BB * HH];
__device__ __half g_w2_h[HH * HH];      // fp16 copy of attn_w[:, H:2H]

// ======================= helpers ===========================================
__device__ __forceinline__ uint32_t smem_u32(const void* p) {
    uint32_t a;
    asm("{ .reg .u64 t; cvta.to.shared.u64 t, %1; cvt.u32.u64 %0, t; }"
        : "=r"(a) : "l"(p));
    return a;
}
__device__ __forceinline__ void ldsm4(uint32_t addr, uint32_t r[4]) {
    asm volatile("ldmatrix.sync.aligned.m8n8.x4.shared.b16 {%0,%1,%2,%3}, [%4];"
                 : "=r"(r[0]), "=r"(r[1]), "=r"(r[2]), "=r"(r[3]) : "r"(addr));
}
__device__ __forceinline__ void mma_f16(float* c, const uint32_t* a, const uint32_t* b) {
    asm volatile(
        "mma.sync.aligned.m16n8k16.row.col.f32.f16.f16.f32 "
        "{%0,%1,%2,%3}, {%4,%5,%6,%7}, {%8,%9}, {%0,%1,%2,%3};"
        : "+f"(c[0]), "+f"(c[1]), "+f"(c[2]), "+f"(c[3])
        : "r"(a[0]), "r"(a[1]), "r"(a[2]), "r"(a[3]), "r"(b[0]), "r"(b[1]));
}
// pack 8 fp32 -> 8 fp16 (uint4)
__device__ __forceinline__ uint4 cvt8h(float4 a, float4 b) {
    union { __half2 h[4]; uint4 u; } P;
    P.h[0] = __floats2half2_rn(a.x, a.y);
    P.h[1] = __floats2half2_rn(a.z, a.w);
    P.h[2] = __floats2half2_rn(b.x, b.y);
    P.h[3] = __floats2half2_rn(b.z, b.w);
    return P.u;
}
__device__ __forceinline__ float tanha(float x) {
    float e = __expf(2.f * x);
    return 1.f - __fdividef(2.f, e + 1.f);
}

// ======================= conv_w2 (fp32 -> fp16, W2 slice) ==================
__global__ void conv_w2_kernel(const float* __restrict__ attn_w) {
    size_t e = ((size_t)blockIdx.x * 256 + threadIdx.x) * 8;
    int h = (int)(e >> 10), k = (int)(e & 1023);
    const float* src = attn_w + (size_t)h * (2 * HH) + HH + k;
    float4 a = *(const float4*)src;
    float4 b = *(const float4*)(src + 4);
    *(uint4*)(g_w2_h + e) = cvt8h(a, b);
}

// ======================= zero scratch (scores + split-K accumulators) ======
__global__ void zero_scratch_kernel() {
    int i = blockIdx.x * 256 + threadIdx.x;
    if (i < BB * SS) g_scores[i] = 0.f;
    if (i < BB * HH) g_p[i] = 0.f;
    if (i < BB * 3 * HH) { g_gi[i] = 0.f; g_gh[i] = 0.f; }
}

// ======================= energy GEMM (fp16 single-product) =================
// scores[b,s] += sum_{n in tile} v[n]*tanh( p[b,n] + sum_k enc[b,s,k]*W2[n,k] )
// CTA tile 128(rows) x 128(n), KC=32, 8 warps (warp tile 32x64).
// A (enc) is fp32, converted to fp16 in the loader; B (W2) pre-converted fp16.
__global__ void __launch_bounds__(256)
attn_energy_h(const float* __restrict__ Ef,
              const __half* __restrict__ W,
              const float* __restrict__ v_w) {
    __shared__ __align__(16) char sm[2 * 128 * RS];   // A, B fp16 tiles
    __shared__ float psh[128], vsh[128];
    __shared__ float red[128][2];

    const int tid = threadIdx.x, lane = tid & 31, wid = tid >> 5;
    const int n0 = blockIdx.x * 128;
    const int r0 = blockIdx.y * 128;
    const int b  = blockIdx.y >> 2;
    const int wm = wid >> 1, wn = wid & 1;

    if (tid < 128) {
        psh[tid] = g_p[b * HH + n0 + tid];
        vsh[tid] = v_w[n0 + tid];
    }

    char* smA = sm;
    char* smB = sm + 128 * RS;
    const uint32_t uA = smem_u32(smA);
    const uint32_t uB = uA + 128 * RS;

    const float*  Ab = Ef + (size_t)r0 * HH;
    const __half* Bb = W + (size_t)n0 * HH;

    // per-stage footprint: A 128 rows x 32 fp32 (as 2 float4/seg), B 128 rows x 32 fp16
    // t=0,1 -> A segs (512), t=2,3 -> B segs (512); seg = 16B fp16 = 8 elems
    float4 pa[2][2];
    uint4  pb[2];
#pragma unroll
    for (int t = 0; t < 2; t++) {
        int id = t * 256 + tid;
        int row = id >> 2, seg = id & 3;
        const float* p = Ab + (size_t)row * HH + seg * 8;
        pa[t][0] = *(const float4*)p;
        pa[t][1] = *(const float4*)(p + 4);
    }
#pragma unroll
    for (int t = 0; t < 2; t++) {
        int id = t * 256 + tid;
        int row = id >> 2, seg = id & 3;
        pb[t] = *(const uint4*)(Bb + (size_t)row * HH + seg * 8);
    }

    float acc[2][8][4];
#pragma unroll
    for (int i = 0; i < 2; i++)
#pragma unroll
        for (int j = 0; j < 8; j++)
#pragma unroll
            for (int q = 0; q < 4; q++) acc[i][j][q] = 0.f;

    for (int s = 0; s < 32; s++) {
        __syncthreads();
#pragma unroll
        for (int t = 0; t < 2; t++) {
            int id = t * 256 + tid;
            int row = id >> 2, seg = id & 3;
            *(uint4*)(smA + row * RS + seg * 16) = cvt8h(pa[t][0], pa[t][1]);
        }
#pragma unroll
        for (int t = 0; t < 2; t++) {
            int id = t * 256 + tid;
            int row = id >> 2, seg = id & 3;
            *(uint4*)(smB + row * RS + seg * 16) = pb[t];
        }
        __syncthreads();
        if (s < 31) {
            int k0 = (s + 1) * 32;
#pragma unroll
            for (int t = 0; t < 2; t++) {
                int id = t * 256 + tid;
                int row = id >> 2, seg = id & 3;
                const float* p = Ab + (size_t)row * HH + k0 + seg * 8;
                pa[t][0] = *(const float4*)p;
                pa[t][1] = *(const float4*)(p + 4);
            }
#pragma unroll
            for (int t = 0; t < 2; t++) {
                int id = t * 256 + tid;
                int row = id >> 2, seg = id & 3;
                pb[t] = *(const uint4*)(Bb + (size_t)row * HH + k0 + seg * 8);
            }
        }
#pragma unroll
        for (int ks = 0; ks < 2; ks++) {
            uint32_t ah[2][4];
#pragma unroll
            for (int mf = 0; mf < 2; mf++) {
                int row = wm * 32 + mf * 16 + (lane & 7) + ((lane >> 3) & 1) * 8;
                int kb  = ks * 32 + ((lane >> 4) & 1) * 16;
                ldsm4(uA + row * RS + kb, ah[mf]);
            }
            uint32_t bh[8][2];
#pragma unroll
            for (int np = 0; np < 4; np++) {
                int row = wn * 64 + np * 16 + ((lane >> 4) & 1) * 8 + (lane & 7);
                int kb  = ks * 32 + ((lane >> 3) & 1) * 16;
                uint32_t r4[4];
                ldsm4(uB + row * RS + kb, r4);
                bh[2*np][0] = r4[0]; bh[2*np][1] = r4[1];
                bh[2*np+1][0] = r4[2]; bh[2*np+1][1] = r4[3];
            }
#pragma unroll
            for (int mf = 0; mf < 2; mf++)
#pragma unroll
                for (int nf = 0; nf < 8; nf++)
                    mma_f16(acc[mf][nf], ah[mf], bh[nf]);
        }
    }

    // epilogue: tanh + v-weighted reduction over n
    __syncthreads();
    float sum[2][2] = {{0.f, 0.f}, {0.f, 0.f}};
#pragma unroll
    for (int mf = 0; mf < 2; mf++)
#pragma unroll
        for (int nf = 0; nf < 8; nf++) {
            int n = wn * 64 + nf * 8 + (lane & 3) * 2;
            float v0 = vsh[n], v1 = vsh[n + 1];
            float p0 = psh[n], p1 = psh[n + 1];
            sum[mf][0] += v0 * tanha(acc[mf][nf][0] + p0)
                        + v1 * tanha(acc[mf][nf][1] + p1);
            sum[mf][1] += v0 * tanha(acc[mf][nf][2] + p0)
                        + v1 * tanha(acc[mf][nf][3] + p1);
        }
#pragma unroll
    for (int mf = 0; mf < 2; mf++)
#pragma unroll
        for (int half = 0; half < 2; half++) {
            float sv = sum[mf][half];
            sv += __shfl_xor_sync(0xFFFFFFFF, sv, 1);
            sv += __shfl_xor_sync(0xFFFFFFFF, sv, 2);
            if ((lane & 3) == 0) {
                int r = wm * 32 + mf * 16 + half * 8 + (lane >> 2);
                red[r][wn] = sv;
            }
        }
    __syncthreads();
    if (tid < 128)
        atomicAdd(&g_scores[r0 + tid], red[tid][0] + red[tid][1]);
}

// ======================= generic M=64 GEMM (fp16 single-product) ===========
// C[64,N] = bias + A[64,K] @ B[N,K]^T. fp32 inputs converted to fp16 in loader.
// grid.y = split-K slices (atomicAdd, C pre-zeroed, bias by slice 0);
// grid.y==1 -> direct store. CTA tile 64x128, warp tile 32x32.
__global__ void __launch_bounds__(256)
gemm64_h(const float* __restrict__ A, int lda,
         const float* __restrict__ Bw, int ldb,
         const float* __restrict__ bias,
         float* __restrict__ C, int N, int K) {
    __shared__ __align__(16) char sm[64 * RS + 128 * RS];   // A, B fp16

    const int tid = threadIdx.x, lane = tid & 31, wid = tid >> 5;
    const int n0 = blockIdx.x * 128;
    const int wm = wid & 1, wn = wid >> 1;
    const int nk = K / gridDim.y;
    const int kbeg = blockIdx.y * nk;

    char* smA = sm;
    char* smB = sm + 64 * RS;
    const uint32_t uA = smem_u32(smA);
    const uint32_t uB = uA + 64 * RS;

    // per stage: A 64 rows x 4 segs = 256 ids; B 128 rows x 4 segs = 512 ids
    float4 pf[3][2];
#pragma unroll
    for (int t = 0; t < 3; t++) {
        int id = t * 256 + tid;
        if (id < 256) {
            int row = id >> 2, seg = id & 3;
            const float* p = A + (size_t)row * lda + kbeg + seg * 8;
            pf[t][0] = *(const float4*)p;
            pf[t][1] = *(const float4*)(p + 4);
        } else {
            int id2 = id - 256;
            int row = id2 >> 2, seg = id2 & 3;
            int rg = n0 + row;
            if (rg < N) {
                const float* p = Bw + (size_t)rg * ldb + kbeg + seg * 8;
                pf[t][0] = *(const float4*)p;
                pf[t][1] = *(const float4*)(p + 4);
            } else {
                pf[t][0] = make_float4(0.f, 0.f, 0.f, 0.f);
                pf[t][1] = make_float4(0.f, 0.f, 0.f, 0.f);
            }
        }
    }

    float acc[2][4][4];
#pragma unroll
    for (int i = 0; i < 2; i++)
#pragma unroll
        for (int j = 0; j < 4; j++)
#pragma unroll
            for (int q = 0; q < 4; q++) acc[i][j][q] = 0.f;

    const int nstages = nk / 32;
    for (int s = 0; s < nstages; s++) {
        __syncthreads();
#pragma unroll
        for (int t = 0; t < 3; t++) {
            int id = t * 256 + tid;
            char* dst;
            int row, seg;
            if (id < 256) { row = id >> 2; seg = id & 3; dst = smA; }
            else { int id2 = id - 256; row = id2 >> 2; seg = id2 & 3; dst = smB; }
            *(uint4*)(dst + row * RS + seg * 16) = cvt8h(pf[t][0], pf[t][1]);
        }
        __syncthreads();
        if (s < nstages - 1) {
            int k0 = kbeg + (s + 1) * 32;
#pragma unroll
            for (int t = 0; t < 3; t++) {
                int id = t * 256 + tid;
                if (id < 256) {
                    int row = id >> 2, seg = id & 3;
                    const float* p = A + (size_t)row * lda + k0 + seg * 8;
                    pf[t][0] = *(const float4*)p;
                    pf[t][1] = *(const float4*)(p + 4);
                } else {
                    int id2 = id - 256;
                    int row = id2 >> 2, seg = id2 & 3;
                    int rg = n0 + row;
                    if (rg < N) {
                        const float* p = Bw + (size_t)rg * ldb + k0 + seg * 8;
                        pf[t][0] = *(const float4*)p;
                        pf[t][1] = *(const float4*)(p + 4);
                    } else {
                        pf[t][0] = make_float4(0.f, 0.f, 0.f, 0.f);
                        pf[t][1] = make_float4(0.f, 0.f, 0.f, 0.f);
                    }
                }
            }
        }
#pragma unroll
        for (int ks = 0; ks < 2; ks++) {
            uint32_t ah[2][4];
#pragma unroll
            for (int mf = 0; mf < 2; mf++) {
                int row = wm * 32 + mf * 16 + (lane & 7) + ((lane >> 3) & 1) * 8;
                int kb  = ks * 32 + ((lane >> 4) & 1) * 16;
                ldsm4(uA + row * RS + kb, ah[mf]);
            }
            uint32_t bh[4][2];
#pragma unroll
            for (int np = 0; np < 2; np++) {
                int row = wn * 32 + np * 16 + ((lane >> 4) & 1) * 8 + (lane & 7);
                int kb  = ks * 32 + ((lane >> 3) & 1) * 16;
                uint32_t r4[4];
                ldsm4(uB + row * RS + kb, r4);
                bh[2*np][0] = r4[0]; bh[2*np][1] = r4[1];
                bh[2*np+1][0] = r4[2]; bh[2*np+1][1] = r4[3];
            }
#pragma unroll
            for (int mf = 0; mf < 2; mf++)
#pragma unroll
                for (int nf = 0; nf < 4; nf++)
                    mma_f16(acc[mf][nf], ah[mf], bh[nf]);
        }
    }

    const bool direct = (gridDim.y == 1);
    const bool addb = (blockIdx.y == 0);
#pragma unroll
    for (int mf = 0; mf < 2; mf++) {
        int m = wm * 32 + mf * 16 + (lane >> 2);
#pragma unroll
        for (int nf = 0; nf < 4; nf++) {
            int n = n0 + wn * 32 + nf * 8 + (lane & 3) * 2;
            if (n < N) {
                float bb0 = addb ? bias[n] : 0.f;
                if (direct) {
                    C[(size_t)m * N + n]       = acc[mf][nf][0] + bb0;
                    C[(size_t)(m + 8) * N + n] = acc[mf][nf][2] + bb0;
                } else {
                    atomicAdd(&C[(size_t)m * N + n],       acc[mf][nf][0] + bb0);
                    atomicAdd(&C[(size_t)(m + 8) * N + n], acc[mf][nf][2] + bb0);
                }
            }
            if (n + 1 < N) {
                float bb1 = addb ? bias[n + 1] : 0.f;
                if (direct) {
                    C[(size_t)m * N + n + 1]       = acc[mf][nf][1] + bb1;
                    C[(size_t)(m + 8) * N + n + 1] = acc[mf][nf][3] + bb1;
                } else {
                    atomicAdd(&C[(size_t)m * N + n + 1],       acc[mf][nf][1] + bb1);
                    atomicAdd(&C[(size_t)(m + 8) * N + n + 1], acc[mf][nf][3] + bb1);
                }
            }
        }
    }
}

// ======================= softmax ===========================================
__global__ void softmax_kernel(float* __restrict__ attn_out) {
    int b = blockIdx.x;
    int tid = threadIdx.x;
    __shared__ float sh[256];
    float v0 = g_scores[b * SS + tid];
    float v1 = g_scores[b * SS + 256 + tid];
    float m = fmaxf(v0, v1);
    sh[tid] = m;
    __syncthreads();
    for (int o = 128; o > 0; o >>= 1) {
        if (tid < o) sh[tid] = fmaxf(sh[tid], sh[tid + o]);
        __syncthreads();
    }
    m = sh[0];
    __syncthreads();
    float e0 = expf(v0 - m), e1 = expf(v1 - m);
    sh[tid] = e0 + e1;
    __syncthreads();
    for (int o = 128; o > 0; o >>= 1) {
        if (tid < o) sh[tid] += sh[tid + o];
        __syncthreads();
    }
    float inv = 1.f / sh[0];
    attn_out[b * SS + tid]       = e0 * inv;
    attn_out[b * SS + 256 + tid] = e1 * inv;
}

// ======================= context ===========================================
__global__ void context_kernel(const float* __restrict__ enc,
                               const float* __restrict__ attn) {
    int b = blockIdx.x;
    int h = blockIdx.y * 128 + threadIdx.x;
    __shared__ float ash[SS];
    for (int i = threadIdx.x; i < SS; i += 128) ash[i] = attn[b * SS + i];
    __syncthreads();
    const float* ep = enc + (size_t)b * SS * HH + h;
    float acc = 0.f;
#pragma unroll 4
    for (int s = 0; s < SS; s++) acc += ash[s] * ep[(size_t)s * HH];
    g_context[b * HH + h] = acc;
}

// ======================= x = [emb ; context] ================================
__global__ void xbuild_kernel(const int* __restrict__ ids,
                              const float* __restrict__ emb) {
    int idx = blockIdx.x * 256 + threadIdx.x;
    int b = idx >> 11, k = idx & 2047;
    float v;
    if (k < HH) v = emb[(size_t)ids[b] * HH + k];
    else        v = g_context[b * HH + (k - HH)];
    g_x[idx] = v;
}

// ======================= GRU elementwise ====================================
__global__ void hnew_kernel(const float* __restrict__ hidden,
                            float* __restrict__ out_hidden) {
    int idx = blockIdx.x * 256 + threadIdx.x;
    int b = idx >> 10, h = idx & 1023;
    int base = b * 3 * HH;
    float ir  = g_gi[base + h];
    float iz  = g_gi[base + HH + h];
    float in_ = g_gi[base + 2 * HH + h];
    float hr  = g_gh[base + h];
    float hz  = g_gh[base + HH + h];
    float hn  = g_gh[base + 2 * HH + h];
    float r = 1.f / (1.f + expf(-(ir + hr)));
    float z = 1.f / (1.f + expf(-(iz + hz)));
    float n = tanhf(in_ + r * hn);
    float ho = hidden[idx];
    float hv = (1.f - z) * n + z * ho;
    g_hnew[idx] = hv;
    out_hidden[idx] = hv;
}

// ======================= launch =============================================
extern "C" void kernel_launch(void* const* d_in, const int* in_sizes, int n_in,
                              void* d_out, int out_size) {
    const int*   ids    = (const int*)d_in[0];
    const float* hidden = (const float*)d_in[1];
    const float* enc    = (const float*)d_in[2];
    const float* emb    = (const float*)d_in[3];
    const float* attn_w = (const float*)d_in[4];
    const float* attn_b = (const float*)d_in[5];
    const float* v_w    = (const float*)d_in[6];
    const float* w_ih   = (const float*)d_in[7];
    const float* w_hh   = (const float*)d_in[8];
    const float* b_ih   = (const float*)d_in[9];
    const float* b_hh   = (const float*)d_in[10];
    const float* out_w  = (const float*)d_in[11];
    const float* out_b  = (const float*)d_in[12];

    float* out = (float*)d_out;
    float* out_pred   = out;
    float* out_hidden = out + (size_t)BB * VV;
    float* out_attn   = out_hidden + (size_t)BB * HH;

    float *p_p, *p_x, *p_gi, *p_gh, *p_hnew;
    cudaGetSymbolAddress((void**)&p_p,    g_p);
    cudaGetSymbolAddress((void**)&p_x,    g_x);
    cudaGetSymbolAddress((void**)&p_gi,   g_gi);
    cudaGetSymbolAddress((void**)&p_gh,   g_gh);
    cudaGetSymbolAddress((void**)&p_hnew, g_hnew);
    __half* p_wh;
    cudaGetSymbolAddress((void**)&p_wh, g_w2_h);

    // 1. W2 fp16 conversion + zero split-K accumulators / scores
    conv_w2_kernel<<<(HH * HH) / 2048, 256>>>(attn_w);
    zero_scratch_kernel<<<(BB * 3 * HH) / 256, 256>>>();

    // 2. p = hidden @ W1^T + attn_b   (split-K 8; W1 = attn_w[:, :H])
    gemm64_h<<<dim3(HH / 128, 8), 256>>>(hidden, HH, attn_w, 2 * HH,
                                         attn_b, p_p, HH, HH);

    // 3. energy GEMM (fp16, enc converted inline) + fused tanh/v -> scores
    attn_energy_h<<<dim3(HH / 128, BS / 128), 256>>>(enc, p_wh, v_w);

    // 4. softmax -> attn output
    softmax_kernel<<<BB, 256>>>(out_attn);

    // 5. context = attn @ enc
    context_kernel<<<dim3(BB, HH / 128), 128>>>(enc, out_attn);

    // 6. x = [embedded ; context]
    xbuild_kernel<<<(BB * 2 * HH) / 256, 256>>>(ids, emb);

    // 7. GRU gate GEMMs (split-K 4)
    gemm64_h<<<dim3((3 * HH) / 128, 4), 256>>>(p_x, 2 * HH, w_ih, 2 * HH,
                                               b_ih, p_gi, 3 * HH, 2 * HH);
    gemm64_h<<<dim3((3 * HH) / 128, 4), 256>>>(hidden, HH, w_hh, HH,
                                               b_hh, p_gh, 3 * HH, HH);

    // 8. GRU nonlinearity -> h_new (also writes hidden output)
    hnew_kernel<<<(BB * HH) / 256, 256>>>(hidden, out_hidden);

    // 9. prediction = h_new @ out_w^T + out_b  (direct-store, out_w BW-bound)
    gemm64_h<<<dim3((VV + 127) / 128, 1), 256>>>(p_hnew, HH, out_w, HH,
                                                 out_b, out_pred, VV, HH);
}